// round 1
// baseline (speedup 1.0000x reference)
#include <cuda_runtime.h>
#include <math_constants.h>

#define B_ 2
#define T_ 2048
#define C_ 2048
#define H_ 16
#define D_ 128
#define M_ (B_*T_)   // 4096 rows

// Scratch (static device globals — no runtime allocation)
__device__ float g_q[(size_t)M_ * C_];
__device__ float g_k[(size_t)M_ * C_];
__device__ float g_v[(size_t)M_ * C_];
__device__ float g_o[(size_t)M_ * C_];

// ---------------------------------------------------------------------------
// SGEMM:  C[M,N] = A[M,K] @ B[N,K]^T   (both row-major, dot of rows)
// 128x128 tile, BK=16, 256 threads, 8x8 per-thread
// ---------------------------------------------------------------------------
__global__ __launch_bounds__(256, 2) void sgemm_nt(
    const float* __restrict__ A, const float* __restrict__ Bm,
    float* __restrict__ C, int M, int N, int K)
{
    __shared__ float As[16][128];
    __shared__ float Bs[16][128];
    const int tid = threadIdx.x;
    const int tx = tid & 15, ty = tid >> 4;
    const float* Ab = A  + (size_t)blockIdx.y * 128 * K;
    const float* Bb = Bm + (size_t)blockIdx.x * 128 * K;

    float acc[8][8];
    #pragma unroll
    for (int i = 0; i < 8; i++)
        #pragma unroll
        for (int j = 0; j < 8; j++) acc[i][j] = 0.f;

    for (int k0 = 0; k0 < K; k0 += 16) {
        #pragma unroll
        for (int it = 0; it < 2; it++) {
            int idx = tid + it * 256;       // 0..511 float4 slots
            int r   = idx >> 2;             // tile row 0..127
            int c4  = (idx & 3) << 2;       // k offset 0,4,8,12
            float4 va = *(const float4*)(Ab + (size_t)r * K + k0 + c4);
            As[c4+0][r] = va.x; As[c4+1][r] = va.y; As[c4+2][r] = va.z; As[c4+3][r] = va.w;
            float4 vb = *(const float4*)(Bb + (size_t)r * K + k0 + c4);
            Bs[c4+0][r] = vb.x; Bs[c4+1][r] = vb.y; Bs[c4+2][r] = vb.z; Bs[c4+3][r] = vb.w;
        }
        __syncthreads();
        #pragma unroll
        for (int kk = 0; kk < 16; kk++) {
            float a[8], b[8];
            *(float4*)(a)   = *(const float4*)&As[kk][ty*8];
            *(float4*)(a+4) = *(const float4*)&As[kk][ty*8+4];
            *(float4*)(b)   = *(const float4*)&Bs[kk][tx*8];
            *(float4*)(b+4) = *(const float4*)&Bs[kk][tx*8+4];
            #pragma unroll
            for (int i = 0; i < 8; i++)
                #pragma unroll
                for (int j = 0; j < 8; j++)
                    acc[i][j] = fmaf(a[i], b[j], acc[i][j]);
        }
        __syncthreads();
    }

    float* Cb = C + (size_t)(blockIdx.y*128 + ty*8) * N + blockIdx.x*128 + tx*8;
    #pragma unroll
    for (int i = 0; i < 8; i++) {
        *(float4*)(Cb + (size_t)i*N)     = make_float4(acc[i][0], acc[i][1], acc[i][2], acc[i][3]);
        *(float4*)(Cb + (size_t)i*N + 4) = make_float4(acc[i][4], acc[i][5], acc[i][6], acc[i][7]);
    }
}

// ---------------------------------------------------------------------------
// Fused per-head RMSNorm + RoPE on q and k (in place).
// One warp per (token, head): 32 lanes x 4 elements = D=128.
// Lane owns d = {lane, lane+32} of first half paired with {lane+64, lane+96}.
// ---------------------------------------------------------------------------
__global__ __launch_bounds__(256) void rmsnorm_rope(
    float* __restrict__ q, float* __restrict__ k,
    const float* __restrict__ cs, const float* __restrict__ sn)
{
    int gw   = (blockIdx.x * blockDim.x + threadIdx.x) >> 5;
    int lane = threadIdx.x & 31;
    if (gw >= B_ * T_ * H_) return;
    int h  = gw % H_;
    int bt = gw / H_;
    int t  = bt % T_;

    const float c0 = cs[t*64 + lane], c1 = cs[t*64 + lane + 32];
    const float s0 = sn[t*64 + lane], s1 = sn[t*64 + lane + 32];

    #pragma unroll
    for (int w = 0; w < 2; w++) {
        float* base = (w ? k : q) + (size_t)bt * C_ + h * D_;
        float x0 = base[lane], x1 = base[lane+32], x2 = base[lane+64], x3 = base[lane+96];
        float ss = x0*x0 + x1*x1 + x2*x2 + x3*x3;
        #pragma unroll
        for (int m = 16; m; m >>= 1) ss += __shfl_xor_sync(0xffffffffu, ss, m);
        float r = rsqrtf(ss * (1.0f/128.0f) + 1.1920929e-7f);
        x0 *= r; x1 *= r; x2 *= r; x3 *= r;
        base[lane]    =  x0*c0 + x2*s0;
        base[lane+32] =  x1*c1 + x3*s1;
        base[lane+64] = -x0*s0 + x2*c0;
        base[lane+96] = -x1*s1 + x3*c1;
    }
}

// ---------------------------------------------------------------------------
// Flash attention (causal), fp32. One CTA per (b, h, 64-query tile).
// Q,K stored transposed in smem [128][68] (pad 68 -> conflict-free LDS.128).
// V reuses the K buffer (union) in natural [64][128] layout.
// ---------------------------------------------------------------------------
#define QS 68

__global__ __launch_bounds__(256, 2) void flash_attn(
    const float* __restrict__ qp, const float* __restrict__ kp,
    const float* __restrict__ vp, float* __restrict__ op)
{
    extern __shared__ float sm[];
    float* Qt  = sm;                 // [128][QS]  Q^T
    float* KtV = sm + 128*QS;        // K^T [128][QS]  OR  V [64][128]
    float* Ps  = sm + 2*128*QS;      // P   [64][QS]

    const int tid = threadIdx.x;
    const int tx = tid & 15, ty = tid >> 4;
    const int qb = blockIdx.x;
    const int b  = blockIdx.y >> 4, h = blockIdx.y & 15;
    const size_t rowbase = (size_t)b * T_;

    // Load Q tile transposed
    const float* qg = qp + (rowbase + qb*64) * C_ + h * D_;
    #pragma unroll
    for (int it = 0; it < 8; it++) {
        int idx = tid + it*256;
        int r = idx >> 5;               // query row 0..63
        int c = (idx & 31) << 2;        // d offset 0..124
        float4 vv = *(const float4*)(qg + (size_t)r * C_ + c);
        Qt[(c+0)*QS + r] = vv.x; Qt[(c+1)*QS + r] = vv.y;
        Qt[(c+2)*QS + r] = vv.z; Qt[(c+3)*QS + r] = vv.w;
    }

    float m_i[4], l_i[4], acc[4][8];
    #pragma unroll
    for (int i = 0; i < 4; i++) {
        m_i[i] = -CUDART_INF_F; l_i[i] = 0.f;
        #pragma unroll
        for (int j = 0; j < 8; j++) acc[i][j] = 0.f;
    }
    const float scale = 0.088388347648318447f;   // 1/sqrt(128)

    for (int kt = 0; kt <= qb; kt++) {
        __syncthreads();   // previous PV done with KtV(V) and Ps
        // Load K tile transposed
        const float* kg = kp + (rowbase + kt*64) * C_ + h * D_;
        #pragma unroll
        for (int it = 0; it < 8; it++) {
            int idx = tid + it*256;
            int r = idx >> 5;
            int c = (idx & 31) << 2;
            float4 vv = *(const float4*)(kg + (size_t)r * C_ + c);
            KtV[(c+0)*QS + r] = vv.x; KtV[(c+1)*QS + r] = vv.y;
            KtV[(c+2)*QS + r] = vv.z; KtV[(c+3)*QS + r] = vv.w;
        }
        __syncthreads();

        // S = Q K^T  (4x4 fragment per thread)
        float s[4][4];
        #pragma unroll
        for (int i = 0; i < 4; i++)
            #pragma unroll
            for (int j = 0; j < 4; j++) s[i][j] = 0.f;
        for (int kk = 0; kk < 128; kk++) {
            float a_[4], b_[4];
            *(float4*)a_ = *(const float4*)&Qt[kk*QS + ty*4];
            *(float4*)b_ = *(const float4*)&KtV[kk*QS + tx*4];
            #pragma unroll
            for (int i = 0; i < 4; i++)
                #pragma unroll
                for (int j = 0; j < 4; j++)
                    s[i][j] = fmaf(a_[i], b_[j], s[i][j]);
        }

        // mask + scale + online softmax (rows = ty*4+i, reduce over 16 tx lanes)
        const int qi0 = qb*64 + ty*4;
        const int kj0 = kt*64 + tx*4;
        #pragma unroll
        for (int i = 0; i < 4; i++) {
            #pragma unroll
            for (int j = 0; j < 4; j++) {
                if (kj0 + j > qi0 + i) s[i][j] = -CUDART_INF_F;
                else                   s[i][j] *= scale;
            }
            float tm = fmaxf(fmaxf(s[i][0], s[i][1]), fmaxf(s[i][2], s[i][3]));
            #pragma unroll
            for (int msk = 1; msk < 16; msk <<= 1)
                tm = fmaxf(tm, __shfl_xor_sync(0xffffffffu, tm, msk, 16));
            float mn    = fmaxf(m_i[i], tm);
            float alpha = __expf(m_i[i] - mn);
            float rs = 0.f;
            #pragma unroll
            for (int j = 0; j < 4; j++) {
                float p = __expf(s[i][j] - mn);
                s[i][j] = p; rs += p;
            }
            #pragma unroll
            for (int msk = 1; msk < 16; msk <<= 1)
                rs += __shfl_xor_sync(0xffffffffu, rs, msk, 16);
            l_i[i] = l_i[i]*alpha + rs;
            m_i[i] = mn;
            #pragma unroll
            for (int jj = 0; jj < 8; jj++) acc[i][jj] *= alpha;
            *(float4*)&Ps[(ty*4+i)*QS + tx*4] = make_float4(s[i][0], s[i][1], s[i][2], s[i][3]);
        }
        __syncthreads();   // S compute done with KtV(K^T); Ps published

        // Load V tile (natural layout), overwriting KtV
        const float* vg = vp + (rowbase + kt*64) * C_ + h * D_;
        #pragma unroll
        for (int it = 0; it < 8; it++) {
            int idx = tid + it*256;
            int r = idx >> 5;
            int c = (idx & 31) << 2;
            *(float4*)&KtV[r*128 + c] = *(const float4*)(vg + (size_t)r * C_ + c);
        }
        __syncthreads();

        // O += P @ V   (cols = tx*8+jj)
        for (int kk = 0; kk < 64; kk++) {
            float p_[4];
            #pragma unroll
            for (int i = 0; i < 4; i++) p_[i] = Ps[(ty*4+i)*QS + kk];
            float vv[8];
            *(float4*)(vv)   = *(const float4*)&KtV[kk*128 + tx*8];
            *(float4*)(vv+4) = *(const float4*)&KtV[kk*128 + tx*8 + 4];
            #pragma unroll
            for (int i = 0; i < 4; i++)
                #pragma unroll
                for (int jj = 0; jj < 8; jj++)
                    acc[i][jj] = fmaf(p_[i], vv[jj], acc[i][jj]);
        }
    }

    // Epilogue: normalize and write
    float* og = op + (rowbase + qb*64) * C_ + h * D_;
    #pragma unroll
    for (int i = 0; i < 4; i++) {
        float inv = 1.0f / l_i[i];
        int r = ty*4 + i;
        *(float4*)(og + (size_t)r*C_ + tx*8)     =
            make_float4(acc[i][0]*inv, acc[i][1]*inv, acc[i][2]*inv, acc[i][3]*inv);
        *(float4*)(og + (size_t)r*C_ + tx*8 + 4) =
            make_float4(acc[i][4]*inv, acc[i][5]*inv, acc[i][6]*inv, acc[i][7]*inv);
    }
}

// ---------------------------------------------------------------------------
extern "C" void kernel_launch(void* const* d_in, const int* in_sizes, int n_in,
                              void* d_out, int out_size)
{
    (void)in_sizes; (void)n_in; (void)out_size;
    const float* x  = (const float*)d_in[0];
    const float* cs = (const float*)d_in[1];
    const float* sn = (const float*)d_in[2];
    const float* Wq = (const float*)d_in[3];
    const float* Wk = (const float*)d_in[4];
    const float* Wv = (const float*)d_in[5];
    const float* Wo = (const float*)d_in[6];
    float* out = (float*)d_out;

    float *q, *k, *v, *o;
    cudaGetSymbolAddress((void**)&q, g_q);
    cudaGetSymbolAddress((void**)&k, g_k);
    cudaGetSymbolAddress((void**)&v, g_v);
    cudaGetSymbolAddress((void**)&o, g_o);

    const int FLASH_SMEM = (2*128*QS + 64*QS) * (int)sizeof(float);  // 87040 B
    cudaFuncSetAttribute(flash_attn, cudaFuncAttributeMaxDynamicSharedMemorySize, FLASH_SMEM);

    dim3 gemmGrid(C_/128, M_/128);   // (16, 32)
    sgemm_nt<<<gemmGrid, 256>>>(x, Wq, q, M_, C_, C_);
    sgemm_nt<<<gemmGrid, 256>>>(x, Wk, k, M_, C_, C_);
    sgemm_nt<<<gemmGrid, 256>>>(x, Wv, v, M_, C_, C_);

    rmsnorm_rope<<<(B_*T_*H_)/8, 256>>>(q, k, cs, sn);

    flash_attn<<<dim3(T_/64, B_*H_), 256, FLASH_SMEM>>>(q, k, v, o);

    sgemm_nt<<<gemmGrid, 256>>>(o, Wo, out, M_, C_, C_);
}

// round 2
// speedup vs baseline: 1.6958x; 1.6958x over previous
#include <cuda_runtime.h>
#include <cuda_bf16.h>
#include <math_constants.h>
#include <cstdint>

#define B_ 2
#define T_ 2048
#define C_ 2048
#define H_ 16
#define D_ 128
#define M_ (B_*T_)   // 4096 rows

// ---------------- scratch (static device globals) ----------------
__device__ float g_q[(size_t)M_ * C_];
__device__ float g_k[(size_t)M_ * C_];
__device__ float g_v[(size_t)M_ * C_];
__device__ float g_o[(size_t)M_ * C_];
__device__ __nv_bfloat16 g_xh[(size_t)M_ * C_];
__device__ __nv_bfloat16 g_xl[(size_t)M_ * C_];
__device__ __nv_bfloat16 g_oh[(size_t)M_ * C_];
__device__ __nv_bfloat16 g_ol[(size_t)M_ * C_];
__device__ __nv_bfloat16 g_wh[4][(size_t)C_ * C_];
__device__ __nv_bfloat16 g_wl[4][(size_t)C_ * C_];

// ---------------------------------------------------------------------------
// fp32 -> bf16 hi/lo split
// ---------------------------------------------------------------------------
__global__ __launch_bounds__(256) void split_f32(
    const float4* __restrict__ src, uint2* __restrict__ hi, uint2* __restrict__ lo, int n4)
{
    int i = blockIdx.x * blockDim.x + threadIdx.x;
    if (i >= n4) return;
    float4 v = src[i];
    __nv_bfloat16 h0 = __float2bfloat16(v.x);
    __nv_bfloat16 h1 = __float2bfloat16(v.y);
    __nv_bfloat16 h2 = __float2bfloat16(v.z);
    __nv_bfloat16 h3 = __float2bfloat16(v.w);
    __nv_bfloat16 l0 = __float2bfloat16(v.x - __bfloat162float(h0));
    __nv_bfloat16 l1 = __float2bfloat16(v.y - __bfloat162float(h1));
    __nv_bfloat16 l2 = __float2bfloat16(v.z - __bfloat162float(h2));
    __nv_bfloat16 l3 = __float2bfloat16(v.w - __bfloat162float(h3));
    union { __nv_bfloat162 b2[2]; uint2 u; } ph, pl;
    ph.b2[0] = __halves2bfloat162(h0, h1); ph.b2[1] = __halves2bfloat162(h2, h3);
    pl.b2[0] = __halves2bfloat162(l0, l1); pl.b2[1] = __halves2bfloat162(l2, l3);
    hi[i] = ph.u;
    lo[i] = pl.u;
}

// ---------------------------------------------------------------------------
// bf16-split tensor-core GEMM:  C[M,N] = A[M,K] @ B[N,K]^T  (3-term hi/lo)
// 128x128 tile, BK=32, 256 threads (8 warps, 4x2), cp.async double buffer
// ---------------------------------------------------------------------------
#define SA 40                       // padded row stride (bf16 elems) -> conflict-free ldmatrix
#define TERM (128*SA)               // elems per (term, tile)
#define STG  (4*TERM)               // elems per stage (Ah, Al, Bh, Bl)
#define GEMM_SMEM (2*STG*2)         // bytes: 81920

__device__ __forceinline__ void ldmx4(uint32_t &r0, uint32_t &r1, uint32_t &r2, uint32_t &r3, uint32_t addr) {
    asm volatile("ldmatrix.sync.aligned.m8n8.x4.shared.b16 {%0,%1,%2,%3}, [%4];"
                 : "=r"(r0), "=r"(r1), "=r"(r2), "=r"(r3) : "r"(addr));
}
__device__ __forceinline__ void mma16816(float* d, const uint32_t* a, const uint32_t* b) {
    asm volatile("mma.sync.aligned.m16n8k16.row.col.f32.bf16.bf16.f32 "
                 "{%0,%1,%2,%3},{%4,%5,%6,%7},{%8,%9},{%0,%1,%2,%3};"
                 : "+f"(d[0]), "+f"(d[1]), "+f"(d[2]), "+f"(d[3])
                 : "r"(a[0]), "r"(a[1]), "r"(a[2]), "r"(a[3]), "r"(b[0]), "r"(b[1]));
}
__device__ __forceinline__ void cp16(uint32_t saddr, const void* g) {
    asm volatile("cp.async.cg.shared.global [%0], [%1], 16;" :: "r"(saddr), "l"(g));
}

__global__ __launch_bounds__(256) void bgemm_split(
    const __nv_bfloat16* __restrict__ Ah, const __nv_bfloat16* __restrict__ Al,
    const __nv_bfloat16* __restrict__ Bh, const __nv_bfloat16* __restrict__ Bl,
    float* __restrict__ Cc, int M, int N, int K)
{
    extern __shared__ __nv_bfloat16 sm2[];
    const int tid  = threadIdx.x;
    const int lane = tid & 31, wid = tid >> 5;
    const int wm = wid & 3, wn = wid >> 1 & 0; // placeholder (recomputed below)
    (void)wm; (void)wn;
    const int warp_m = wid & 3;        // 0..3 -> m offset *32
    const int warp_n = wid >> 2;       // 0..1 -> n offset *64
    const int bm = blockIdx.y, bn = blockIdx.x;
    const uint32_t sbase = (uint32_t)__cvta_generic_to_shared(sm2);

    const int lr = tid >> 2;           // 0..63 (row, +64 on 2nd iter)
    const int lc = (tid & 3) << 3;     // k offset 0,8,16,24

    float acc[2][8][4];
    #pragma unroll
    for (int i = 0; i < 2; i++)
        #pragma unroll
        for (int j = 0; j < 8; j++)
            #pragma unroll
            for (int q = 0; q < 4; q++) acc[i][j][q] = 0.f;

    auto issue = [&](int s, int k0) {
        #pragma unroll
        for (int it = 0; it < 2; it++) {
            int r = lr + it * 64;
            size_t ga = (size_t)(bm * 128 + r) * K + k0 + lc;
            size_t gb = (size_t)(bn * 128 + r) * K + k0 + lc;
            uint32_t so = (uint32_t)(s * STG + r * SA + lc);
            cp16(sbase + 2u * (so + 0 * TERM), Ah + ga);
            cp16(sbase + 2u * (so + 1 * TERM), Al + ga);
            cp16(sbase + 2u * (so + 2 * TERM), Bh + gb);
            cp16(sbase + 2u * (so + 3 * TERM), Bl + gb);
        }
        asm volatile("cp.async.commit_group;");
    };

    issue(0, 0);

    int s = 0;
    for (int k0 = 0; k0 < K; k0 += 32, s ^= 1) {
        if (k0 + 32 < K) {
            issue(s ^ 1, k0 + 32);
            asm volatile("cp.async.wait_group 1;");
        } else {
            asm volatile("cp.async.wait_group 0;");
        }
        __syncthreads();

        #pragma unroll
        for (int kk = 0; kk < 32; kk += 16) {
            const int mlane = lane & 15;
            const int klA = kk + ((lane >> 4) << 3);
            uint32_t a[2][2][4];
            #pragma unroll
            for (int t = 0; t < 2; t++)
                #pragma unroll
                for (int i = 0; i < 2; i++) {
                    uint32_t ad = sbase + 2u * (uint32_t)(s * STG + t * TERM +
                                  (warp_m * 32 + i * 16 + mlane) * SA + klA);
                    ldmx4(a[t][i][0], a[t][i][1], a[t][i][2], a[t][i][3], ad);
                }
            const int nlane = (lane & 7) + ((lane >> 4) << 3);
            const int klB = kk + (((lane >> 3) & 1) << 3);
            uint32_t b[8][2];
            // B hi
            #pragma unroll
            for (int jt = 0; jt < 4; jt++) {
                uint32_t ad = sbase + 2u * (uint32_t)(s * STG + 2 * TERM +
                              (warp_n * 64 + jt * 16 + nlane) * SA + klB);
                ldmx4(b[2*jt][0], b[2*jt][1], b[2*jt+1][0], b[2*jt+1][1], ad);
            }
            #pragma unroll
            for (int i = 0; i < 2; i++)
                #pragma unroll
                for (int j = 0; j < 8; j++) mma16816(acc[i][j], a[0][i], b[j]);  // hi*hi
            #pragma unroll
            for (int i = 0; i < 2; i++)
                #pragma unroll
                for (int j = 0; j < 8; j++) mma16816(acc[i][j], a[1][i], b[j]);  // lo*hi
            // B lo
            #pragma unroll
            for (int jt = 0; jt < 4; jt++) {
                uint32_t ad = sbase + 2u * (uint32_t)(s * STG + 3 * TERM +
                              (warp_n * 64 + jt * 16 + nlane) * SA + klB);
                ldmx4(b[2*jt][0], b[2*jt][1], b[2*jt+1][0], b[2*jt+1][1], ad);
            }
            #pragma unroll
            for (int i = 0; i < 2; i++)
                #pragma unroll
                for (int j = 0; j < 8; j++) mma16816(acc[i][j], a[0][i], b[j]);  // hi*lo
        }
        __syncthreads();
    }

    // epilogue
    #pragma unroll
    for (int i = 0; i < 2; i++) {
        int row = bm * 128 + warp_m * 32 + i * 16 + (lane >> 2);
        #pragma unroll
        for (int j = 0; j < 8; j++) {
            int col = bn * 128 + warp_n * 64 + j * 8 + ((lane & 3) << 1);
            *(float2*)&Cc[(size_t)row * N + col]       = make_float2(acc[i][j][0], acc[i][j][1]);
            *(float2*)&Cc[(size_t)(row + 8) * N + col] = make_float2(acc[i][j][2], acc[i][j][3]);
        }
    }
}

// ---------------------------------------------------------------------------
// Fused per-head RMSNorm + RoPE on q and k (in place). One warp per (token, head).
// ---------------------------------------------------------------------------
__global__ __launch_bounds__(256) void rmsnorm_rope(
    float* __restrict__ q, float* __restrict__ k,
    const float* __restrict__ cs, const float* __restrict__ sn)
{
    int gw   = (blockIdx.x * blockDim.x + threadIdx.x) >> 5;
    int lane = threadIdx.x & 31;
    if (gw >= B_ * T_ * H_) return;
    int h  = gw % H_;
    int bt = gw / H_;
    int t  = bt % T_;

    const float c0 = cs[t*64 + lane], c1 = cs[t*64 + lane + 32];
    const float s0 = sn[t*64 + lane], s1 = sn[t*64 + lane + 32];

    #pragma unroll
    for (int w = 0; w < 2; w++) {
        float* base = (w ? k : q) + (size_t)bt * C_ + h * D_;
        float x0 = base[lane], x1 = base[lane+32], x2 = base[lane+64], x3 = base[lane+96];
        float ss = x0*x0 + x1*x1 + x2*x2 + x3*x3;
        #pragma unroll
        for (int m = 16; m; m >>= 1) ss += __shfl_xor_sync(0xffffffffu, ss, m);
        float r = rsqrtf(ss * (1.0f/128.0f) + 1.1920929e-7f);
        x0 *= r; x1 *= r; x2 *= r; x3 *= r;
        base[lane]    =  x0*c0 + x2*s0;
        base[lane+32] =  x1*c1 + x3*s1;
        base[lane+64] = -x0*s0 + x2*c0;
        base[lane+96] = -x1*s1 + x3*c1;
    }
}

// ---------------------------------------------------------------------------
// Flash attention (causal), fp32.
// ---------------------------------------------------------------------------
#define QS 68

__global__ __launch_bounds__(256, 2) void flash_attn(
    const float* __restrict__ qp, const float* __restrict__ kp,
    const float* __restrict__ vp, float* __restrict__ op)
{
    extern __shared__ float sm[];
    float* Qt  = sm;                 // [128][QS]  Q^T
    float* KtV = sm + 128*QS;        // K^T [128][QS]  OR  V [64][128]
    float* Ps  = sm + 2*128*QS;      // P   [64][QS]

    const int tid = threadIdx.x;
    const int tx = tid & 15, ty = tid >> 4;
    const int qb = blockIdx.x;
    const int b  = blockIdx.y >> 4, h = blockIdx.y & 15;
    const size_t rowbase = (size_t)b * T_;

    const float* qg = qp + (rowbase + qb*64) * C_ + h * D_;
    #pragma unroll
    for (int it = 0; it < 8; it++) {
        int idx = tid + it*256;
        int r = idx >> 5;
        int c = (idx & 31) << 2;
        float4 vv = *(const float4*)(qg + (size_t)r * C_ + c);
        Qt[(c+0)*QS + r] = vv.x; Qt[(c+1)*QS + r] = vv.y;
        Qt[(c+2)*QS + r] = vv.z; Qt[(c+3)*QS + r] = vv.w;
    }

    float m_i[4], l_i[4], acc[4][8];
    #pragma unroll
    for (int i = 0; i < 4; i++) {
        m_i[i] = -CUDART_INF_F; l_i[i] = 0.f;
        #pragma unroll
        for (int j = 0; j < 8; j++) acc[i][j] = 0.f;
    }
    const float scale = 0.088388347648318447f;

    for (int kt = 0; kt <= qb; kt++) {
        __syncthreads();
        const float* kg = kp + (rowbase + kt*64) * C_ + h * D_;
        #pragma unroll
        for (int it = 0; it < 8; it++) {
            int idx = tid + it*256;
            int r = idx >> 5;
            int c = (idx & 31) << 2;
            float4 vv = *(const float4*)(kg + (size_t)r * C_ + c);
            KtV[(c+0)*QS + r] = vv.x; KtV[(c+1)*QS + r] = vv.y;
            KtV[(c+2)*QS + r] = vv.z; KtV[(c+3)*QS + r] = vv.w;
        }
        __syncthreads();

        float s[4][4];
        #pragma unroll
        for (int i = 0; i < 4; i++)
            #pragma unroll
            for (int j = 0; j < 4; j++) s[i][j] = 0.f;
        for (int kk = 0; kk < 128; kk++) {
            float a_[4], b_[4];
            *(float4*)a_ = *(const float4*)&Qt[kk*QS + ty*4];
            *(float4*)b_ = *(const float4*)&KtV[kk*QS + tx*4];
            #pragma unroll
            for (int i = 0; i < 4; i++)
                #pragma unroll
                for (int j = 0; j < 4; j++)
                    s[i][j] = fmaf(a_[i], b_[j], s[i][j]);
        }

        const int qi0 = qb*64 + ty*4;
        const int kj0 = kt*64 + tx*4;
        #pragma unroll
        for (int i = 0; i < 4; i++) {
            #pragma unroll
            for (int j = 0; j < 4; j++) {
                if (kj0 + j > qi0 + i) s[i][j] = -CUDART_INF_F;
                else                   s[i][j] *= scale;
            }
            float tm = fmaxf(fmaxf(s[i][0], s[i][1]), fmaxf(s[i][2], s[i][3]));
            #pragma unroll
            for (int msk = 1; msk < 16; msk <<= 1)
                tm = fmaxf(tm, __shfl_xor_sync(0xffffffffu, tm, msk, 16));
            float mn    = fmaxf(m_i[i], tm);
            float alpha = __expf(m_i[i] - mn);
            float rs = 0.f;
            #pragma unroll
            for (int j = 0; j < 4; j++) {
                float p = __expf(s[i][j] - mn);
                s[i][j] = p; rs += p;
            }
            #pragma unroll
            for (int msk = 1; msk < 16; msk <<= 1)
                rs += __shfl_xor_sync(0xffffffffu, rs, msk, 16);
            l_i[i] = l_i[i]*alpha + rs;
            m_i[i] = mn;
            #pragma unroll
            for (int jj = 0; jj < 8; jj++) acc[i][jj] *= alpha;
            *(float4*)&Ps[(ty*4+i)*QS + tx*4] = make_float4(s[i][0], s[i][1], s[i][2], s[i][3]);
        }
        __syncthreads();

        const float* vg = vp + (rowbase + kt*64) * C_ + h * D_;
        #pragma unroll
        for (int it = 0; it < 8; it++) {
            int idx = tid + it*256;
            int r = idx >> 5;
            int c = (idx & 31) << 2;
            *(float4*)&KtV[r*128 + c] = *(const float4*)(vg + (size_t)r * C_ + c);
        }
        __syncthreads();

        for (int kk = 0; kk < 64; kk++) {
            float p_[4];
            #pragma unroll
            for (int i = 0; i < 4; i++) p_[i] = Ps[(ty*4+i)*QS + kk];
            float vv[8];
            *(float4*)(vv)   = *(const float4*)&KtV[kk*128 + tx*8];
            *(float4*)(vv+4) = *(const float4*)&KtV[kk*128 + tx*8 + 4];
            #pragma unroll
            for (int i = 0; i < 4; i++)
                #pragma unroll
                for (int jj = 0; jj < 8; jj++)
                    acc[i][jj] = fmaf(p_[i], vv[jj], acc[i][jj]);
        }
    }

    float* og = op + (rowbase + qb*64) * C_ + h * D_;
    #pragma unroll
    for (int i = 0; i < 4; i++) {
        float inv = 1.0f / l_i[i];
        int r = ty*4 + i;
        *(float4*)(og + (size_t)r*C_ + tx*8)     =
            make_float4(acc[i][0]*inv, acc[i][1]*inv, acc[i][2]*inv, acc[i][3]*inv);
        *(float4*)(og + (size_t)r*C_ + tx*8 + 4) =
            make_float4(acc[i][4]*inv, acc[i][5]*inv, acc[i][6]*inv, acc[i][7]*inv);
    }
}

// ---------------------------------------------------------------------------
extern "C" void kernel_launch(void* const* d_in, const int* in_sizes, int n_in,
                              void* d_out, int out_size)
{
    (void)in_sizes; (void)n_in; (void)out_size;
    const float* x  = (const float*)d_in[0];
    const float* cs = (const float*)d_in[1];
    const float* sn = (const float*)d_in[2];
    const float* Ws[4] = { (const float*)d_in[3], (const float*)d_in[4],
                           (const float*)d_in[5], (const float*)d_in[6] };
    float* out = (float*)d_out;

    float *q, *k, *v, *o;
    __nv_bfloat16 *xh, *xl, *oh, *ol, *wh, *wl;
    cudaGetSymbolAddress((void**)&q, g_q);
    cudaGetSymbolAddress((void**)&k, g_k);
    cudaGetSymbolAddress((void**)&v, g_v);
    cudaGetSymbolAddress((void**)&o, g_o);
    cudaGetSymbolAddress((void**)&xh, g_xh);
    cudaGetSymbolAddress((void**)&xl, g_xl);
    cudaGetSymbolAddress((void**)&oh, g_oh);
    cudaGetSymbolAddress((void**)&ol, g_ol);
    cudaGetSymbolAddress((void**)&wh, g_wh);
    cudaGetSymbolAddress((void**)&wl, g_wl);

    cudaFuncSetAttribute(bgemm_split, cudaFuncAttributeMaxDynamicSharedMemorySize, GEMM_SMEM);
    const int FLASH_SMEM = (2*128*QS + 64*QS) * (int)sizeof(float);
    cudaFuncSetAttribute(flash_attn, cudaFuncAttributeMaxDynamicSharedMemorySize, FLASH_SMEM);

    const int nx4 = (M_ * C_) / 4;     // 2097152
    const int nw4 = (C_ * C_) / 4;     // 1048576
    split_f32<<<nx4/256, 256>>>((const float4*)x, (uint2*)xh, (uint2*)xl, nx4);
    for (int w = 0; w < 4; w++)
        split_f32<<<nw4/256, 256>>>((const float4*)Ws[w],
                                    (uint2*)(wh + (size_t)w * C_ * C_),
                                    (uint2*)(wl + (size_t)w * C_ * C_), nw4);

    dim3 gemmGrid(C_/128, M_/128);   // (16, 32)
    bgemm_split<<<gemmGrid, 256, GEMM_SMEM>>>(xh, xl, wh + 0*(size_t)C_*C_, wl + 0*(size_t)C_*C_, q, M_, C_, C_);
    bgemm_split<<<gemmGrid, 256, GEMM_SMEM>>>(xh, xl, wh + 1*(size_t)C_*C_, wl + 1*(size_t)C_*C_, k, M_, C_, C_);
    bgemm_split<<<gemmGrid, 256, GEMM_SMEM>>>(xh, xl, wh + 2*(size_t)C_*C_, wl + 2*(size_t)C_*C_, v, M_, C_, C_);

    rmsnorm_rope<<<(B_*T_*H_)/8, 256>>>(q, k, cs, sn);

    flash_attn<<<dim3(T_/64, B_*H_), 256, FLASH_SMEM>>>(q, k, v, o);

    split_f32<<<nx4/256, 256>>>((const float4*)o, (uint2*)oh, (uint2*)ol, nx4);
    bgemm_split<<<gemmGrid, 256, GEMM_SMEM>>>(oh, ol, wh + 3*(size_t)C_*C_, wl + 3*(size_t)C_*C_, out, M_, C_, C_);
}

// round 3
// speedup vs baseline: 2.7428x; 1.6174x over previous
#include <cuda_runtime.h>
#include <cuda_bf16.h>
#include <math_constants.h>
#include <cstdint>

#define B_ 2
#define T_ 2048
#define C_ 2048
#define H_ 16
#define D_ 128
#define M_ (B_*T_)   // 4096 rows

// ---------------- scratch (static device globals) ----------------
__device__ float g_q[(size_t)M_ * C_];
__device__ float g_k[(size_t)M_ * C_];
__device__ __nv_bfloat16 g_xh[(size_t)M_ * C_];
__device__ __nv_bfloat16 g_xl[(size_t)M_ * C_];
__device__ __nv_bfloat16 g_qh[(size_t)M_ * C_];
__device__ __nv_bfloat16 g_ql[(size_t)M_ * C_];
__device__ __nv_bfloat16 g_kh[(size_t)M_ * C_];
__device__ __nv_bfloat16 g_kl[(size_t)M_ * C_];
__device__ __nv_bfloat16 g_vh[(size_t)M_ * C_];
__device__ __nv_bfloat16 g_vl[(size_t)M_ * C_];
__device__ __nv_bfloat16 g_oh[(size_t)M_ * C_];
__device__ __nv_bfloat16 g_ol[(size_t)M_ * C_];
__device__ __nv_bfloat16 g_wh[4][(size_t)C_ * C_];
__device__ __nv_bfloat16 g_wl[4][(size_t)C_ * C_];

union BU { __nv_bfloat162 b; uint32_t u; };

__device__ __forceinline__ uint32_t pack_hi(float x, float y) {
    BU u; u.b = __floats2bfloat162_rn(x, y); return u.u;
}
__device__ __forceinline__ uint32_t pack_lo(float x, float y, uint32_t hi) {
    BU h; h.u = hi;
    BU u; u.b = __floats2bfloat162_rn(x - __bfloat162float(h.b.x),
                                      y - __bfloat162float(h.b.y));
    return u.u;
}

// ---------------------------------------------------------------------------
// fp32 -> bf16 hi/lo split
// ---------------------------------------------------------------------------
__global__ __launch_bounds__(256) void split_f32(
    const float4* __restrict__ src, uint2* __restrict__ hi, uint2* __restrict__ lo, int n4)
{
    int i = blockIdx.x * blockDim.x + threadIdx.x;
    if (i >= n4) return;
    float4 v = src[i];
    uint32_t h0 = pack_hi(v.x, v.y), h1 = pack_hi(v.z, v.w);
    uint32_t l0 = pack_lo(v.x, v.y, h0), l1 = pack_lo(v.z, v.w, h1);
    hi[i] = make_uint2(h0, h1);
    lo[i] = make_uint2(l0, l1);
}

// ---------------------------------------------------------------------------
// MMA / ldmatrix / cp.async primitives
// ---------------------------------------------------------------------------
__device__ __forceinline__ void ldmx4(uint32_t &r0, uint32_t &r1, uint32_t &r2, uint32_t &r3, uint32_t addr) {
    asm volatile("ldmatrix.sync.aligned.m8n8.x4.shared.b16 {%0,%1,%2,%3}, [%4];"
                 : "=r"(r0), "=r"(r1), "=r"(r2), "=r"(r3) : "r"(addr));
}
__device__ __forceinline__ void ldmx4t(uint32_t &r0, uint32_t &r1, uint32_t &r2, uint32_t &r3, uint32_t addr) {
    asm volatile("ldmatrix.sync.aligned.m8n8.x4.trans.shared.b16 {%0,%1,%2,%3}, [%4];"
                 : "=r"(r0), "=r"(r1), "=r"(r2), "=r"(r3) : "r"(addr));
}
__device__ __forceinline__ void mma16816(float* d, const uint32_t* a, const uint32_t* b) {
    asm volatile("mma.sync.aligned.m16n8k16.row.col.f32.bf16.bf16.f32 "
                 "{%0,%1,%2,%3},{%4,%5,%6,%7},{%8,%9},{%0,%1,%2,%3};"
                 : "+f"(d[0]), "+f"(d[1]), "+f"(d[2]), "+f"(d[3])
                 : "r"(a[0]), "r"(a[1]), "r"(a[2]), "r"(a[3]), "r"(b[0]), "r"(b[1]));
}
__device__ __forceinline__ void cp16(uint32_t saddr, const void* g) {
    asm volatile("cp.async.cg.shared.global [%0], [%1], 16;" :: "r"(saddr), "l"(g));
}

// ---------------------------------------------------------------------------
// bf16-split tensor-core GEMM:  C[M,N] = A[M,K] @ B[N,K]^T  (3-term hi/lo)
// OMODE 0: fp32 out.  OMODE 1: bf16 hi/lo out.
// ---------------------------------------------------------------------------
#define SA 40
#define TERM (128*SA)
#define STG  (4*TERM)
#define GEMM_SMEM (2*STG*2)

template<int OMODE>
__global__ __launch_bounds__(256) void bgemm_split(
    const __nv_bfloat16* __restrict__ Ah, const __nv_bfloat16* __restrict__ Al,
    const __nv_bfloat16* __restrict__ Bh, const __nv_bfloat16* __restrict__ Bl,
    float* __restrict__ Cc, __nv_bfloat16* __restrict__ Ch, __nv_bfloat16* __restrict__ Cl,
    int M, int N, int K)
{
    extern __shared__ __nv_bfloat16 sm2[];
    const int tid  = threadIdx.x;
    const int lane = tid & 31, wid = tid >> 5;
    const int warp_m = wid & 3;
    const int warp_n = wid >> 2;
    const int bm = blockIdx.y, bn = blockIdx.x;
    const uint32_t sbase = (uint32_t)__cvta_generic_to_shared(sm2);

    const int lr = tid >> 2;
    const int lc = (tid & 3) << 3;

    float acc[2][8][4];
    #pragma unroll
    for (int i = 0; i < 2; i++)
        #pragma unroll
        for (int j = 0; j < 8; j++)
            #pragma unroll
            for (int q = 0; q < 4; q++) acc[i][j][q] = 0.f;

    auto issue = [&](int s, int k0) {
        #pragma unroll
        for (int it = 0; it < 2; it++) {
            int r = lr + it * 64;
            size_t ga = (size_t)(bm * 128 + r) * K + k0 + lc;
            size_t gb = (size_t)(bn * 128 + r) * K + k0 + lc;
            uint32_t so = (uint32_t)(s * STG + r * SA + lc);
            cp16(sbase + 2u * (so + 0 * TERM), Ah + ga);
            cp16(sbase + 2u * (so + 1 * TERM), Al + ga);
            cp16(sbase + 2u * (so + 2 * TERM), Bh + gb);
            cp16(sbase + 2u * (so + 3 * TERM), Bl + gb);
        }
        asm volatile("cp.async.commit_group;");
    };

    issue(0, 0);

    int s = 0;
    for (int k0 = 0; k0 < K; k0 += 32, s ^= 1) {
        if (k0 + 32 < K) {
            issue(s ^ 1, k0 + 32);
            asm volatile("cp.async.wait_group 1;");
        } else {
            asm volatile("cp.async.wait_group 0;");
        }
        __syncthreads();

        #pragma unroll
        for (int kk = 0; kk < 32; kk += 16) {
            const int mlane = lane & 15;
            const int klA = kk + ((lane >> 4) << 3);
            uint32_t a[2][2][4];
            #pragma unroll
            for (int t = 0; t < 2; t++)
                #pragma unroll
                for (int i = 0; i < 2; i++) {
                    uint32_t ad = sbase + 2u * (uint32_t)(s * STG + t * TERM +
                                  (warp_m * 32 + i * 16 + mlane) * SA + klA);
                    ldmx4(a[t][i][0], a[t][i][1], a[t][i][2], a[t][i][3], ad);
                }
            const int nlane = (lane & 7) + ((lane >> 4) << 3);
            const int klB = kk + (((lane >> 3) & 1) << 3);
            uint32_t b[8][2];
            #pragma unroll
            for (int jt = 0; jt < 4; jt++) {
                uint32_t ad = sbase + 2u * (uint32_t)(s * STG + 2 * TERM +
                              (warp_n * 64 + jt * 16 + nlane) * SA + klB);
                ldmx4(b[2*jt][0], b[2*jt][1], b[2*jt+1][0], b[2*jt+1][1], ad);
            }
            #pragma unroll
            for (int i = 0; i < 2; i++)
                #pragma unroll
                for (int j = 0; j < 8; j++) mma16816(acc[i][j], a[0][i], b[j]);
            #pragma unroll
            for (int i = 0; i < 2; i++)
                #pragma unroll
                for (int j = 0; j < 8; j++) mma16816(acc[i][j], a[1][i], b[j]);
            #pragma unroll
            for (int jt = 0; jt < 4; jt++) {
                uint32_t ad = sbase + 2u * (uint32_t)(s * STG + 3 * TERM +
                              (warp_n * 64 + jt * 16 + nlane) * SA + klB);
                ldmx4(b[2*jt][0], b[2*jt][1], b[2*jt+1][0], b[2*jt+1][1], ad);
            }
            #pragma unroll
            for (int i = 0; i < 2; i++)
                #pragma unroll
                for (int j = 0; j < 8; j++) mma16816(acc[i][j], a[0][i], b[j]);
        }
        __syncthreads();
    }

    #pragma unroll
    for (int i = 0; i < 2; i++) {
        int row = bm * 128 + warp_m * 32 + i * 16 + (lane >> 2);
        #pragma unroll
        for (int j = 0; j < 8; j++) {
            int col = bn * 128 + warp_n * 64 + j * 8 + ((lane & 3) << 1);
            if (OMODE == 0) {
                *(float2*)&Cc[(size_t)row * N + col]       = make_float2(acc[i][j][0], acc[i][j][1]);
                *(float2*)&Cc[(size_t)(row + 8) * N + col] = make_float2(acc[i][j][2], acc[i][j][3]);
            } else {
                uint32_t h0 = pack_hi(acc[i][j][0], acc[i][j][1]);
                uint32_t l0 = pack_lo(acc[i][j][0], acc[i][j][1], h0);
                uint32_t h1 = pack_hi(acc[i][j][2], acc[i][j][3]);
                uint32_t l1 = pack_lo(acc[i][j][2], acc[i][j][3], h1);
                *(uint32_t*)&Ch[(size_t)row * N + col]       = h0;
                *(uint32_t*)&Cl[(size_t)row * N + col]       = l0;
                *(uint32_t*)&Ch[(size_t)(row + 8) * N + col] = h1;
                *(uint32_t*)&Cl[(size_t)(row + 8) * N + col] = l1;
            }
        }
    }
}

// ---------------------------------------------------------------------------
// Fused per-head RMSNorm + RoPE; reads fp32 q,k; writes bf16 hi/lo.
// ---------------------------------------------------------------------------
__global__ __launch_bounds__(256) void rmsnorm_rope_bf16(
    const float* __restrict__ q, const float* __restrict__ k,
    const float* __restrict__ cs, const float* __restrict__ sn,
    __nv_bfloat16* __restrict__ qh, __nv_bfloat16* __restrict__ ql,
    __nv_bfloat16* __restrict__ kh, __nv_bfloat16* __restrict__ kl)
{
    int gw   = (blockIdx.x * blockDim.x + threadIdx.x) >> 5;
    int lane = threadIdx.x & 31;
    if (gw >= B_ * T_ * H_) return;
    int h  = gw % H_;
    int bt = gw / H_;
    int t  = bt % T_;

    const float c0 = cs[t*64 + lane], c1 = cs[t*64 + lane + 32];
    const float s0 = sn[t*64 + lane], s1 = sn[t*64 + lane + 32];

    #pragma unroll
    for (int w = 0; w < 2; w++) {
        const float* base = (w ? k : q) + (size_t)bt * C_ + h * D_;
        __nv_bfloat16* oh = (w ? kh : qh) + (size_t)bt * C_ + h * D_;
        __nv_bfloat16* ol = (w ? kl : ql) + (size_t)bt * C_ + h * D_;
        float x0 = base[lane], x1 = base[lane+32], x2 = base[lane+64], x3 = base[lane+96];
        float ss = x0*x0 + x1*x1 + x2*x2 + x3*x3;
        #pragma unroll
        for (int m = 16; m; m >>= 1) ss += __shfl_xor_sync(0xffffffffu, ss, m);
        float r = rsqrtf(ss * (1.0f/128.0f) + 1.1920929e-7f);
        x0 *= r; x1 *= r; x2 *= r; x3 *= r;
        float y0 =  x0*c0 + x2*s0;
        float y1 =  x1*c1 + x3*s1;
        float y2 = -x0*s0 + x2*c0;
        float y3 = -x1*s1 + x3*c1;
        __nv_bfloat16 h0 = __float2bfloat16(y0);
        __nv_bfloat16 h1 = __float2bfloat16(y1);
        __nv_bfloat16 h2 = __float2bfloat16(y2);
        __nv_bfloat16 h3 = __float2bfloat16(y3);
        oh[lane] = h0; oh[lane+32] = h1; oh[lane+64] = h2; oh[lane+96] = h3;
        ol[lane]    = __float2bfloat16(y0 - __bfloat162float(h0));
        ol[lane+32] = __float2bfloat16(y1 - __bfloat162float(h1));
        ol[lane+64] = __float2bfloat16(y2 - __bfloat162float(h2));
        ol[lane+96] = __float2bfloat16(y3 - __bfloat162float(h3));
    }
}

// ---------------------------------------------------------------------------
// Tensor-core flash attention (causal), bf16 hi/lo 3-term, fp32 accum.
// CTA: 128 q rows, 8 warps (16 rows each). Key tiles of 64, double-buffered.
// ---------------------------------------------------------------------------
#define SQ 136
#define FL_QH 0
#define FL_QL (128*SQ)
#define FL_KV (2*128*SQ)
#define FL_STAGE (4*64*SQ)
#define FL_KH 0
#define FL_KL (64*SQ)
#define FL_VH (128*SQ)
#define FL_VL (192*SQ)
#define FLASH_SMEM ((FL_KV + 2*FL_STAGE)*2)   // 208896 bytes

__global__ __launch_bounds__(256, 1) void flash_bf16(
    const __nv_bfloat16* __restrict__ qh, const __nv_bfloat16* __restrict__ ql,
    const __nv_bfloat16* __restrict__ kh, const __nv_bfloat16* __restrict__ kl,
    const __nv_bfloat16* __restrict__ vh, const __nv_bfloat16* __restrict__ vl,
    __nv_bfloat16* __restrict__ oh, __nv_bfloat16* __restrict__ ol)
{
    extern __shared__ __nv_bfloat16 smf[];
    const int tid = threadIdx.x, lane = tid & 31, wid = tid >> 5;
    const int qb = gridDim.x - 1 - blockIdx.x;     // heavy tiles first
    const int b  = blockIdx.y >> 4, h = blockIdx.y & 15;
    const uint32_t sb = (uint32_t)__cvta_generic_to_shared(smf);
    const size_t rowQ = (size_t)b * T_ + (size_t)qb * 128;
    const int colH = h * D_;

    // Q tile load (128 x 128 hi+lo)
    #pragma unroll
    for (int it = 0; it < 8; it++) {
        int idx = tid + it * 256;
        int r = idx >> 4, c = (idx & 15) << 3;
        size_t g = (rowQ + r) * C_ + colH + c;
        cp16(sb + 2u * (uint32_t)(FL_QH + r * SQ + c), qh + g);
        cp16(sb + 2u * (uint32_t)(FL_QL + r * SQ + c), ql + g);
    }

    auto issueKV = [&](int s, int kt) {
        uint32_t st = FL_KV + s * FL_STAGE;
        #pragma unroll
        for (int it = 0; it < 4; it++) {
            int idx = tid + it * 256;
            int r = idx >> 4, c = (idx & 15) << 3;
            size_t g = ((size_t)b * T_ + (size_t)kt * 64 + r) * C_ + colH + c;
            uint32_t so = (uint32_t)(st + r * SQ + c);
            cp16(sb + 2u * (so + FL_KH), kh + g);
            cp16(sb + 2u * (so + FL_KL), kl + g);
            cp16(sb + 2u * (so + FL_VH), vh + g);
            cp16(sb + 2u * (so + FL_VL), vl + g);
        }
        asm volatile("cp.async.commit_group;");
    };

    issueKV(0, 0);   // Q + KV0 in one group

    const int nkt = 2 * qb + 2;
    const int wq = wid * 16;
    const int gq0 = qb * 128 + wq;
    const float scale = 0.088388347648318447f;

    float m0 = -CUDART_INF_F, m1 = -CUDART_INF_F, l0 = 0.f, l1 = 0.f;
    float oacc[16][4];
    #pragma unroll
    for (int j = 0; j < 16; j++)
        #pragma unroll
        for (int e = 0; e < 4; e++) oacc[j][e] = 0.f;

    int s = 0;
    for (int kt = 0; kt < nkt; kt++) {
        if (kt + 1 < nkt) {
            issueKV(s ^ 1, kt + 1);
            asm volatile("cp.async.wait_group 1;");
        } else {
            asm volatile("cp.async.wait_group 0;");
        }
        __syncthreads();

        const int kb = kt * 64;
        if (kb <= gq0 + 15) {
            const uint32_t st = FL_KV + s * FL_STAGE;

            // ---- S = Q K^T (3-term) ----
            float sacc[8][4];
            #pragma unroll
            for (int j = 0; j < 8; j++)
                #pragma unroll
                for (int e = 0; e < 4; e++) sacc[j][e] = 0.f;

            const int mlane = lane & 15;
            const int aoff  = (lane >> 4) << 3;
            const int nlane = (lane & 7) + ((lane >> 4) << 3);
            const int klB   = ((lane >> 3) & 1) << 3;

            #pragma unroll
            for (int c = 0; c < 8; c++) {
                uint32_t ah[4], al[4];
                ldmx4(ah[0], ah[1], ah[2], ah[3],
                      sb + 2u * (uint32_t)(FL_QH + (wq + mlane) * SQ + c * 16 + aoff));
                ldmx4(al[0], al[1], al[2], al[3],
                      sb + 2u * (uint32_t)(FL_QL + (wq + mlane) * SQ + c * 16 + aoff));
                uint32_t bh2[8][2];
                #pragma unroll
                for (int jt = 0; jt < 4; jt++) {
                    uint32_t ad = sb + 2u * (uint32_t)(st + FL_KH + (jt * 16 + nlane) * SQ + c * 16 + klB);
                    ldmx4(bh2[2*jt][0], bh2[2*jt][1], bh2[2*jt+1][0], bh2[2*jt+1][1], ad);
                }
                #pragma unroll
                for (int j = 0; j < 8; j++) mma16816(sacc[j], ah, bh2[j]);
                #pragma unroll
                for (int j = 0; j < 8; j++) mma16816(sacc[j], al, bh2[j]);
                #pragma unroll
                for (int jt = 0; jt < 4; jt++) {
                    uint32_t ad = sb + 2u * (uint32_t)(st + FL_KL + (jt * 16 + nlane) * SQ + c * 16 + klB);
                    ldmx4(bh2[2*jt][0], bh2[2*jt][1], bh2[2*jt+1][0], bh2[2*jt+1][1], ad);
                }
                #pragma unroll
                for (int j = 0; j < 8; j++) mma16816(sacc[j], ah, bh2[j]);
            }

            // ---- mask + scale + online softmax ----
            const bool diag = (kb + 63 > gq0);
            const int r0 = gq0 + (lane >> 2), r1 = r0 + 8;
            float tm0 = -CUDART_INF_F, tm1 = -CUDART_INF_F;
            #pragma unroll
            for (int j = 0; j < 8; j++) {
                int cc = kb + j * 8 + ((lane & 3) << 1);
                float v0 = sacc[j][0] * scale, v1 = sacc[j][1] * scale;
                float v2 = sacc[j][2] * scale, v3 = sacc[j][3] * scale;
                if (diag) {
                    if (cc     > r0) v0 = -CUDART_INF_F;
                    if (cc + 1 > r0) v1 = -CUDART_INF_F;
                    if (cc     > r1) v2 = -CUDART_INF_F;
                    if (cc + 1 > r1) v3 = -CUDART_INF_F;
                }
                sacc[j][0] = v0; sacc[j][1] = v1; sacc[j][2] = v2; sacc[j][3] = v3;
                tm0 = fmaxf(tm0, fmaxf(v0, v1));
                tm1 = fmaxf(tm1, fmaxf(v2, v3));
            }
            tm0 = fmaxf(tm0, __shfl_xor_sync(0xffffffffu, tm0, 1));
            tm0 = fmaxf(tm0, __shfl_xor_sync(0xffffffffu, tm0, 2));
            tm1 = fmaxf(tm1, __shfl_xor_sync(0xffffffffu, tm1, 1));
            tm1 = fmaxf(tm1, __shfl_xor_sync(0xffffffffu, tm1, 2));
            float mn0 = fmaxf(m0, tm0), mn1 = fmaxf(m1, tm1);
            float a0 = __expf(m0 - mn0), a1 = __expf(m1 - mn1);
            float rs0 = 0.f, rs1 = 0.f;
            #pragma unroll
            for (int j = 0; j < 8; j++) {
                float p0 = __expf(sacc[j][0] - mn0);
                float p1 = __expf(sacc[j][1] - mn0);
                float p2 = __expf(sacc[j][2] - mn1);
                float p3 = __expf(sacc[j][3] - mn1);
                sacc[j][0] = p0; sacc[j][1] = p1; sacc[j][2] = p2; sacc[j][3] = p3;
                rs0 += p0 + p1; rs1 += p2 + p3;
            }
            rs0 += __shfl_xor_sync(0xffffffffu, rs0, 1);
            rs0 += __shfl_xor_sync(0xffffffffu, rs0, 2);
            rs1 += __shfl_xor_sync(0xffffffffu, rs1, 1);
            rs1 += __shfl_xor_sync(0xffffffffu, rs1, 2);
            l0 = l0 * a0 + rs0; l1 = l1 * a1 + rs1;
            m0 = mn0; m1 = mn1;
            #pragma unroll
            for (int j = 0; j < 16; j++) {
                oacc[j][0] *= a0; oacc[j][1] *= a0;
                oacc[j][2] *= a1; oacc[j][3] *= a1;
            }

            // ---- P fragments (hi/lo) ----
            uint32_t ph[4][4], pl[4][4];
            #pragma unroll
            for (int c = 0; c < 4; c++) {
                ph[c][0] = pack_hi(sacc[2*c][0],   sacc[2*c][1]);
                pl[c][0] = pack_lo(sacc[2*c][0],   sacc[2*c][1],   ph[c][0]);
                ph[c][1] = pack_hi(sacc[2*c][2],   sacc[2*c][3]);
                pl[c][1] = pack_lo(sacc[2*c][2],   sacc[2*c][3],   ph[c][1]);
                ph[c][2] = pack_hi(sacc[2*c+1][0], sacc[2*c+1][1]);
                pl[c][2] = pack_lo(sacc[2*c+1][0], sacc[2*c+1][1], ph[c][2]);
                ph[c][3] = pack_hi(sacc[2*c+1][2], sacc[2*c+1][3]);
                pl[c][3] = pack_lo(sacc[2*c+1][2], sacc[2*c+1][3], ph[c][3]);
            }

            // ---- O += P V (3-term), V via ldmatrix.trans ----
            const int vrow = ((lane >> 3) & 1) * 8 + (lane & 7);
            const int vcol = (lane >> 4) << 3;
            #pragma unroll
            for (int c = 0; c < 4; c++) {
                #pragma unroll
                for (int dt = 0; dt < 8; dt++) {
                    uint32_t bv[4];
                    uint32_t ad = sb + 2u * (uint32_t)(st + FL_VH + (c * 16 + vrow) * SQ + dt * 16 + vcol);
                    ldmx4t(bv[0], bv[1], bv[2], bv[3], ad);
                    mma16816(oacc[2*dt],   ph[c], bv);
                    mma16816(oacc[2*dt+1], ph[c], bv + 2);
                    mma16816(oacc[2*dt],   pl[c], bv);
                    mma16816(oacc[2*dt+1], pl[c], bv + 2);
                }
                #pragma unroll
                for (int dt = 0; dt < 8; dt++) {
                    uint32_t bv[4];
                    uint32_t ad = sb + 2u * (uint32_t)(st + FL_VL + (c * 16 + vrow) * SQ + dt * 16 + vcol);
                    ldmx4t(bv[0], bv[1], bv[2], bv[3], ad);
                    mma16816(oacc[2*dt],   ph[c], bv);
                    mma16816(oacc[2*dt+1], ph[c], bv + 2);
                }
            }
        }
        __syncthreads();
        s ^= 1;
    }

    // ---- epilogue: O/l -> bf16 hi/lo ----
    float inv0 = 1.0f / l0, inv1 = 1.0f / l1;
    size_t grow0 = (rowQ + wq + (lane >> 2)) * C_;
    size_t grow1 = grow0 + 8 * C_;
    #pragma unroll
    for (int j = 0; j < 16; j++) {
        int col = colH + j * 8 + ((lane & 3) << 1);
        float f0 = oacc[j][0] * inv0, f1 = oacc[j][1] * inv0;
        float f2 = oacc[j][2] * inv1, f3 = oacc[j][3] * inv1;
        uint32_t h0 = pack_hi(f0, f1), h1 = pack_hi(f2, f3);
        *(uint32_t*)&oh[grow0 + col] = h0;
        *(uint32_t*)&ol[grow0 + col] = pack_lo(f0, f1, h0);
        *(uint32_t*)&oh[grow1 + col] = h1;
        *(uint32_t*)&ol[grow1 + col] = pack_lo(f2, f3, h1);
    }
}

// ---------------------------------------------------------------------------
extern "C" void kernel_launch(void* const* d_in, const int* in_sizes, int n_in,
                              void* d_out, int out_size)
{
    (void)in_sizes; (void)n_in; (void)out_size;
    const float* x  = (const float*)d_in[0];
    const float* cs = (const float*)d_in[1];
    const float* sn = (const float*)d_in[2];
    const float* Ws[4] = { (const float*)d_in[3], (const float*)d_in[4],
                           (const float*)d_in[5], (const float*)d_in[6] };
    float* out = (float*)d_out;

    float *q, *k;
    __nv_bfloat16 *xh, *xl, *qh, *ql, *kh, *kl, *vh, *vl, *oh, *ol, *wh, *wl;
    cudaGetSymbolAddress((void**)&q,  g_q);
    cudaGetSymbolAddress((void**)&k,  g_k);
    cudaGetSymbolAddress((void**)&xh, g_xh);
    cudaGetSymbolAddress((void**)&xl, g_xl);
    cudaGetSymbolAddress((void**)&qh, g_qh);
    cudaGetSymbolAddress((void**)&ql, g_ql);
    cudaGetSymbolAddress((void**)&kh, g_kh);
    cudaGetSymbolAddress((void**)&kl, g_kl);
    cudaGetSymbolAddress((void**)&vh, g_vh);
    cudaGetSymbolAddress((void**)&vl, g_vl);
    cudaGetSymbolAddress((void**)&oh, g_oh);
    cudaGetSymbolAddress((void**)&ol, g_ol);
    cudaGetSymbolAddress((void**)&wh, g_wh);
    cudaGetSymbolAddress((void**)&wl, g_wl);

    cudaFuncSetAttribute(bgemm_split<0>, cudaFuncAttributeMaxDynamicSharedMemorySize, GEMM_SMEM);
    cudaFuncSetAttribute(bgemm_split<1>, cudaFuncAttributeMaxDynamicSharedMemorySize, GEMM_SMEM);
    cudaFuncSetAttribute(flash_bf16, cudaFuncAttributeMaxDynamicSharedMemorySize, FLASH_SMEM);

    const int nx4 = (M_ * C_) / 4;
    const int nw4 = (C_ * C_) / 4;
    split_f32<<<nx4/256, 256>>>((const float4*)x, (uint2*)xh, (uint2*)xl, nx4);
    for (int w = 0; w < 4; w++)
        split_f32<<<nw4/256, 256>>>((const float4*)Ws[w],
                                    (uint2*)(wh + (size_t)w * C_ * C_),
                                    (uint2*)(wl + (size_t)w * C_ * C_), nw4);

    dim3 gemmGrid(C_/128, M_/128);
    bgemm_split<0><<<gemmGrid, 256, GEMM_SMEM>>>(xh, xl, wh + 0*(size_t)C_*C_, wl + 0*(size_t)C_*C_, q,   nullptr, nullptr, M_, C_, C_);
    bgemm_split<0><<<gemmGrid, 256, GEMM_SMEM>>>(xh, xl, wh + 1*(size_t)C_*C_, wl + 1*(size_t)C_*C_, k,   nullptr, nullptr, M_, C_, C_);
    bgemm_split<1><<<gemmGrid, 256, GEMM_SMEM>>>(xh, xl, wh + 2*(size_t)C_*C_, wl + 2*(size_t)C_*C_, nullptr, vh, vl,  M_, C_, C_);

    rmsnorm_rope_bf16<<<(B_*T_*H_)/8, 256>>>(q, k, cs, sn, qh, ql, kh, kl);

    flash_bf16<<<dim3(T_/128, B_*H_), 256, FLASH_SMEM>>>(qh, ql, kh, kl, vh, vl, oh, ol);

    bgemm_split<0><<<gemmGrid, 256, GEMM_SMEM>>>(oh, ol, wh + 3*(size_t)C_*C_, wl + 3*(size_t)C_*C_, out, nullptr, nullptr, M_, C_, C_);
}

// round 5
// speedup vs baseline: 3.2297x; 1.1775x over previous
#include <cuda_runtime.h>
#include <cuda_bf16.h>
#include <math_constants.h>
#include <cstdint>

#define B_ 2
#define T_ 2048
#define C_ 2048
#define H_ 16
#define D_ 128
#define M_ (B_*T_)   // 4096 rows

// ---------------- scratch (static device globals) ----------------
__device__ float g_q[(size_t)M_ * C_];
__device__ float g_k[(size_t)M_ * C_];
__device__ __nv_bfloat16 g_xh[(size_t)M_ * C_];
__device__ __nv_bfloat16 g_xl[(size_t)M_ * C_];
__device__ __nv_bfloat16 g_qh[(size_t)M_ * C_];
__device__ __nv_bfloat16 g_ql[(size_t)M_ * C_];
__device__ __nv_bfloat16 g_kh[(size_t)M_ * C_];
__device__ __nv_bfloat16 g_kl[(size_t)M_ * C_];
__device__ __nv_bfloat16 g_vh[(size_t)M_ * C_];
__device__ __nv_bfloat16 g_vl[(size_t)M_ * C_];
__device__ __nv_bfloat16 g_oh[(size_t)M_ * C_];
__device__ __nv_bfloat16 g_ol[(size_t)M_ * C_];
__device__ __nv_bfloat16 g_wh[4][(size_t)C_ * C_];
__device__ __nv_bfloat16 g_wl[4][(size_t)C_ * C_];

union BU { __nv_bfloat162 b; uint32_t u; };

__device__ __forceinline__ uint32_t pack_hi(float x, float y) {
    BU u; u.b = __floats2bfloat162_rn(x, y); return u.u;
}
__device__ __forceinline__ uint32_t pack_lo(float x, float y, uint32_t hi) {
    BU h; h.u = hi;
    BU u; u.b = __floats2bfloat162_rn(x - __bfloat162float(h.b.x),
                                      y - __bfloat162float(h.b.y));
    return u.u;
}

// ---------------------------------------------------------------------------
// fp32 -> bf16 hi/lo split
// ---------------------------------------------------------------------------
__global__ __launch_bounds__(256) void split_f32(
    const float4* __restrict__ src, uint2* __restrict__ hi, uint2* __restrict__ lo, int n4)
{
    int i = blockIdx.x * blockDim.x + threadIdx.x;
    if (i >= n4) return;
    float4 v = src[i];
    uint32_t h0 = pack_hi(v.x, v.y), h1 = pack_hi(v.z, v.w);
    uint32_t l0 = pack_lo(v.x, v.y, h0), l1 = pack_lo(v.z, v.w, h1);
    hi[i] = make_uint2(h0, h1);
    lo[i] = make_uint2(l0, l1);
}

// ---------------------------------------------------------------------------
// primitives
// ---------------------------------------------------------------------------
__device__ __forceinline__ void ldmx4(uint32_t &r0, uint32_t &r1, uint32_t &r2, uint32_t &r3, uint32_t addr) {
    asm volatile("ldmatrix.sync.aligned.m8n8.x4.shared.b16 {%0,%1,%2,%3}, [%4];"
                 : "=r"(r0), "=r"(r1), "=r"(r2), "=r"(r3) : "r"(addr));
}
__device__ __forceinline__ void ldmx4t(uint32_t &r0, uint32_t &r1, uint32_t &r2, uint32_t &r3, uint32_t addr) {
    asm volatile("ldmatrix.sync.aligned.m8n8.x4.trans.shared.b16 {%0,%1,%2,%3}, [%4];"
                 : "=r"(r0), "=r"(r1), "=r"(r2), "=r"(r3) : "r"(addr));
}
__device__ __forceinline__ void mma16816(float* d, const uint32_t* a, const uint32_t* b) {
    asm volatile("mma.sync.aligned.m16n8k16.row.col.f32.bf16.bf16.f32 "
                 "{%0,%1,%2,%3},{%4,%5,%6,%7},{%8,%9},{%0,%1,%2,%3};"
                 : "+f"(d[0]), "+f"(d[1]), "+f"(d[2]), "+f"(d[3])
                 : "r"(a[0]), "r"(a[1]), "r"(a[2]), "r"(a[3]), "r"(b[0]), "r"(b[1]));
}
__device__ __forceinline__ void cp16(uint32_t saddr, const void* g) {
    asm volatile("cp.async.cg.shared.global [%0], [%1], 16;" :: "r"(saddr), "l"(g));
}
// SW64 swizzle for 64-byte rows: XOR 16B-chunk index with row bits
__device__ __forceinline__ uint32_t swz64(uint32_t off) { return off ^ ((off >> 3) & 0x30); }

// ---------------------------------------------------------------------------
// bf16-split tensor-core GEMM:  C[M,N] = A[M,K] @ B[N,K]^T  (3-term hi/lo)
// CTA tile 128x256, BK=32, 8 warps with 64x64 warp tiles, 3-stage cp.async.
// OMODE 0: fp32 out.  OMODE 1: bf16 hi/lo out.
// ---------------------------------------------------------------------------
#define GS_AT 8192                       // A term subtile: 128 rows x 64B
#define GS_BT 16384                      // B term subtile: 256 rows x 64B
#define G_STAGE (2*GS_AT + 2*GS_BT)      // 49152 B
#define G_SMEM (3*G_STAGE)               // 147456 B

template<int OMODE>
__global__ __launch_bounds__(256, 1) void bgemm2(
    const __nv_bfloat16* __restrict__ Ah, const __nv_bfloat16* __restrict__ Al,
    const __nv_bfloat16* __restrict__ Bh, const __nv_bfloat16* __restrict__ Bl,
    float* __restrict__ Cc, __nv_bfloat16* __restrict__ Ch, __nv_bfloat16* __restrict__ Cl,
    int Mm, int Nn, int K)
{
    extern __shared__ __align__(1024) char smg[];
    const int tid = threadIdx.x, lane = tid & 31, wid = tid >> 5;
    const int warp_m = wid & 1;          // 2 -> 64 rows each
    const int warp_n = wid >> 1;         // 4 -> 64 cols each
    const int bm = blockIdx.y, bn = blockIdx.x;
    const uint32_t sb = (uint32_t)__cvta_generic_to_shared(smg);

    float acc[4][8][4];
    #pragma unroll
    for (int i = 0; i < 4; i++)
        #pragma unroll
        for (int j = 0; j < 8; j++)
            #pragma unroll
            for (int e = 0; e < 4; e++) acc[i][j][e] = 0.f;

    auto issue = [&](int s, int k0) {
        const uint32_t st = sb + s * G_STAGE;
        // A: 2 terms x 128 rows x 4 chunks = 1024 chunks
        #pragma unroll
        for (int it = 0; it < 4; it++) {
            int j = tid + it * 256;
            int term = j >> 9;
            int cid  = j & 511;
            int r    = cid >> 2;
            int ch   = cid & 3;
            const __nv_bfloat16* g = (term ? Al : Ah) + (size_t)(bm * 128 + r) * K + k0 + ch * 8;
            cp16(st + term * GS_AT + swz64((uint32_t)(r * 64 + ch * 16)), g);
        }
        // B: 2 terms x 256 rows x 4 chunks = 2048 chunks
        #pragma unroll
        for (int it = 0; it < 8; it++) {
            int j = tid + it * 256;
            int term = j >> 10;
            int cid  = j & 1023;
            int r    = cid >> 2;
            int ch   = cid & 3;
            const __nv_bfloat16* g = (term ? Bl : Bh) + (size_t)(bn * 256 + r) * K + k0 + ch * 8;
            cp16(st + 2 * GS_AT + term * GS_BT + swz64((uint32_t)(r * 64 + ch * 16)), g);
        }
        asm volatile("cp.async.commit_group;");
    };

    const int NS = K / 32;   // 64 stages
    issue(0, 0);
    issue(1, 32);

    const int mlane = lane & 15;
    const int aoff  = (lane >> 4) << 3;
    const int nlane = (lane & 7) + ((lane >> 4) << 3);
    const int klBo  = ((lane >> 3) & 1) << 3;

    for (int i = 0; i < NS; i++) {
        if (i == NS - 1) { asm volatile("cp.async.wait_group 0;"); }
        else             { asm volatile("cp.async.wait_group 1;"); }
        __syncthreads();
        if (i + 2 < NS) issue((i + 2) % 3, (i + 2) * 32);

        const uint32_t st = sb + (i % 3) * G_STAGE;
        #pragma unroll
        for (int kk = 0; kk < 32; kk += 16) {
            uint32_t ah[4][4], al[4][4], b[8][2];
            #pragma unroll
            for (int t = 0; t < 4; t++) {
                uint32_t rb = (uint32_t)((warp_m * 64 + t * 16 + mlane) * 64 + (kk + aoff) * 2);
                ldmx4(ah[t][0], ah[t][1], ah[t][2], ah[t][3], st + 0 * GS_AT + swz64(rb));
                ldmx4(al[t][0], al[t][1], al[t][2], al[t][3], st + 1 * GS_AT + swz64(rb));
            }
            #pragma unroll
            for (int jt = 0; jt < 4; jt++) {
                uint32_t rb = (uint32_t)((warp_n * 64 + jt * 16 + nlane) * 64 + (kk + klBo) * 2);
                ldmx4(b[2*jt][0], b[2*jt][1], b[2*jt+1][0], b[2*jt+1][1],
                      st + 2 * GS_AT + 0 * GS_BT + swz64(rb));
            }
            #pragma unroll
            for (int t = 0; t < 4; t++)
                #pragma unroll
                for (int j = 0; j < 8; j++) mma16816(acc[t][j], ah[t], b[j]);   // hi*hi
            #pragma unroll
            for (int t = 0; t < 4; t++)
                #pragma unroll
                for (int j = 0; j < 8; j++) mma16816(acc[t][j], al[t], b[j]);   // lo*hi
            #pragma unroll
            for (int jt = 0; jt < 4; jt++) {
                uint32_t rb = (uint32_t)((warp_n * 64 + jt * 16 + nlane) * 64 + (kk + klBo) * 2);
                ldmx4(b[2*jt][0], b[2*jt][1], b[2*jt+1][0], b[2*jt+1][1],
                      st + 2 * GS_AT + 1 * GS_BT + swz64(rb));
            }
            #pragma unroll
            for (int t = 0; t < 4; t++)
                #pragma unroll
                for (int j = 0; j < 8; j++) mma16816(acc[t][j], ah[t], b[j]);   // hi*lo
        }
        __syncthreads();
    }

    // epilogue
    #pragma unroll
    for (int t = 0; t < 4; t++) {
        int row = bm * 128 + warp_m * 64 + t * 16 + (lane >> 2);
        #pragma unroll
        for (int j = 0; j < 8; j++) {
            int col = bn * 256 + warp_n * 64 + j * 8 + ((lane & 3) << 1);
            if (OMODE == 0) {
                *(float2*)&Cc[(size_t)row * Nn + col]       = make_float2(acc[t][j][0], acc[t][j][1]);
                *(float2*)&Cc[(size_t)(row + 8) * Nn + col] = make_float2(acc[t][j][2], acc[t][j][3]);
            } else {
                uint32_t h0 = pack_hi(acc[t][j][0], acc[t][j][1]);
                uint32_t l0 = pack_lo(acc[t][j][0], acc[t][j][1], h0);
                uint32_t h1 = pack_hi(acc[t][j][2], acc[t][j][3]);
                uint32_t l1 = pack_lo(acc[t][j][2], acc[t][j][3], h1);
                *(uint32_t*)&Ch[(size_t)row * Nn + col]       = h0;
                *(uint32_t*)&Cl[(size_t)row * Nn + col]       = l0;
                *(uint32_t*)&Ch[(size_t)(row + 8) * Nn + col] = h1;
                *(uint32_t*)&Cl[(size_t)(row + 8) * Nn + col] = l1;
            }
        }
    }
}

// ---------------------------------------------------------------------------
// Fused per-head RMSNorm + RoPE; reads fp32 q,k; writes bf16 hi/lo.
// ---------------------------------------------------------------------------
__global__ __launch_bounds__(256) void rmsnorm_rope_bf16(
    const float* __restrict__ q, const float* __restrict__ k,
    const float* __restrict__ cs, const float* __restrict__ sn,
    __nv_bfloat16* __restrict__ qh, __nv_bfloat16* __restrict__ ql,
    __nv_bfloat16* __restrict__ kh, __nv_bfloat16* __restrict__ kl)
{
    int gw   = (blockIdx.x * blockDim.x + threadIdx.x) >> 5;
    int lane = threadIdx.x & 31;
    if (gw >= B_ * T_ * H_) return;
    int h  = gw % H_;
    int bt = gw / H_;
    int t  = bt % T_;

    const float c0 = cs[t*64 + lane], c1 = cs[t*64 + lane + 32];
    const float s0 = sn[t*64 + lane], s1 = sn[t*64 + lane + 32];

    #pragma unroll
    for (int w = 0; w < 2; w++) {
        const float* base = (w ? k : q) + (size_t)bt * C_ + h * D_;
        __nv_bfloat16* oh = (w ? kh : qh) + (size_t)bt * C_ + h * D_;
        __nv_bfloat16* ol = (w ? kl : ql) + (size_t)bt * C_ + h * D_;
        float x0 = base[lane], x1 = base[lane+32], x2 = base[lane+64], x3 = base[lane+96];
        float ss = x0*x0 + x1*x1 + x2*x2 + x3*x3;
        #pragma unroll
        for (int m = 16; m; m >>= 1) ss += __shfl_xor_sync(0xffffffffu, ss, m);
        float r = rsqrtf(ss * (1.0f/128.0f) + 1.1920929e-7f);
        x0 *= r; x1 *= r; x2 *= r; x3 *= r;
        float y0 =  x0*c0 + x2*s0;
        float y1 =  x1*c1 + x3*s1;
        float y2 = -x0*s0 + x2*c0;
        float y3 = -x1*s1 + x3*c1;
        __nv_bfloat16 h0 = __float2bfloat16(y0);
        __nv_bfloat16 h1 = __float2bfloat16(y1);
        __nv_bfloat16 h2 = __float2bfloat16(y2);
        __nv_bfloat16 h3 = __float2bfloat16(y3);
        oh[lane] = h0; oh[lane+32] = h1; oh[lane+64] = h2; oh[lane+96] = h3;
        ol[lane]    = __float2bfloat16(y0 - __bfloat162float(h0));
        ol[lane+32] = __float2bfloat16(y1 - __bfloat162float(h1));
        ol[lane+64] = __float2bfloat16(y2 - __bfloat162float(h2));
        ol[lane+96] = __float2bfloat16(y3 - __bfloat162float(h3));
    }
}

// ---------------------------------------------------------------------------
// Tensor-core flash attention (causal), bf16 hi/lo 3-term, fp32 accum.
// ---------------------------------------------------------------------------
#define SQ 136
#define FL_QH 0
#define FL_QL (128*SQ)
#define FL_KV (2*128*SQ)
#define FL_STAGE (4*64*SQ)
#define FL_KH 0
#define FL_KL (64*SQ)
#define FL_VH (128*SQ)
#define FL_VL (192*SQ)
#define FLASH_SMEM ((FL_KV + 2*FL_STAGE)*2)   // 208896 bytes

__global__ __launch_bounds__(256, 1) void flash_bf16(
    const __nv_bfloat16* __restrict__ qh, const __nv_bfloat16* __restrict__ ql,
    const __nv_bfloat16* __restrict__ kh, const __nv_bfloat16* __restrict__ kl,
    const __nv_bfloat16* __restrict__ vh, const __nv_bfloat16* __restrict__ vl,
    __nv_bfloat16* __restrict__ oh, __nv_bfloat16* __restrict__ ol)
{
    extern __shared__ __nv_bfloat16 smf[];
    const int tid = threadIdx.x, lane = tid & 31, wid = tid >> 5;
    const int qb = gridDim.x - 1 - blockIdx.x;
    const int b  = blockIdx.y >> 4, h = blockIdx.y & 15;
    const uint32_t sb = (uint32_t)__cvta_generic_to_shared(smf);
    const size_t rowQ = (size_t)b * T_ + (size_t)qb * 128;
    const int colH = h * D_;

    #pragma unroll
    for (int it = 0; it < 8; it++) {
        int idx = tid + it * 256;
        int r = idx >> 4, c = (idx & 15) << 3;
        size_t g = (rowQ + r) * C_ + colH + c;
        cp16(sb + 2u * (uint32_t)(FL_QH + r * SQ + c), qh + g);
        cp16(sb + 2u * (uint32_t)(FL_QL + r * SQ + c), ql + g);
    }

    auto issueKV = [&](int s, int kt) {
        uint32_t st = FL_KV + s * FL_STAGE;
        #pragma unroll
        for (int it = 0; it < 4; it++) {
            int idx = tid + it * 256;
            int r = idx >> 4, c = (idx & 15) << 3;
            size_t g = ((size_t)b * T_ + (size_t)kt * 64 + r) * C_ + colH + c;
            uint32_t so = (uint32_t)(st + r * SQ + c);
            cp16(sb + 2u * (so + FL_KH), kh + g);
            cp16(sb + 2u * (so + FL_KL), kl + g);
            cp16(sb + 2u * (so + FL_VH), vh + g);
            cp16(sb + 2u * (so + FL_VL), vl + g);
        }
        asm volatile("cp.async.commit_group;");
    };

    issueKV(0, 0);

    const int nkt = 2 * qb + 2;
    const int wq = wid * 16;
    const int gq0 = qb * 128 + wq;
    const float scale = 0.088388347648318447f;

    float m0 = -CUDART_INF_F, m1 = -CUDART_INF_F, l0 = 0.f, l1 = 0.f;
    float oacc[16][4];
    #pragma unroll
    for (int j = 0; j < 16; j++)
        #pragma unroll
        for (int e = 0; e < 4; e++) oacc[j][e] = 0.f;

    int s = 0;
    for (int kt = 0; kt < nkt; kt++) {
        if (kt + 1 < nkt) {
            issueKV(s ^ 1, kt + 1);
            asm volatile("cp.async.wait_group 1;");
        } else {
            asm volatile("cp.async.wait_group 0;");
        }
        __syncthreads();

        const int kb = kt * 64;
        if (kb <= gq0 + 15) {
            const uint32_t st = FL_KV + s * FL_STAGE;

            float sacc[8][4];
            #pragma unroll
            for (int j = 0; j < 8; j++)
                #pragma unroll
                for (int e = 0; e < 4; e++) sacc[j][e] = 0.f;

            const int mlane = lane & 15;
            const int aoff  = (lane >> 4) << 3;
            const int nlane = (lane & 7) + ((lane >> 4) << 3);
            const int klB   = ((lane >> 3) & 1) << 3;

            #pragma unroll
            for (int c = 0; c < 8; c++) {
                uint32_t ah[4], al[4];
                ldmx4(ah[0], ah[1], ah[2], ah[3],
                      sb + 2u * (uint32_t)(FL_QH + (wq + mlane) * SQ + c * 16 + aoff));
                ldmx4(al[0], al[1], al[2], al[3],
                      sb + 2u * (uint32_t)(FL_QL + (wq + mlane) * SQ + c * 16 + aoff));
                uint32_t bh2[8][2];
                #pragma unroll
                for (int jt = 0; jt < 4; jt++) {
                    uint32_t ad = sb + 2u * (uint32_t)(st + FL_KH + (jt * 16 + nlane) * SQ + c * 16 + klB);
                    ldmx4(bh2[2*jt][0], bh2[2*jt][1], bh2[2*jt+1][0], bh2[2*jt+1][1], ad);
                }
                #pragma unroll
                for (int j = 0; j < 8; j++) mma16816(sacc[j], ah, bh2[j]);
                #pragma unroll
                for (int j = 0; j < 8; j++) mma16816(sacc[j], al, bh2[j]);
                #pragma unroll
                for (int jt = 0; jt < 4; jt++) {
                    uint32_t ad = sb + 2u * (uint32_t)(st + FL_KL + (jt * 16 + nlane) * SQ + c * 16 + klB);
                    ldmx4(bh2[2*jt][0], bh2[2*jt][1], bh2[2*jt+1][0], bh2[2*jt+1][1], ad);
                }
                #pragma unroll
                for (int j = 0; j < 8; j++) mma16816(sacc[j], ah, bh2[j]);
            }

            const bool diag = (kb + 63 > gq0);
            const int r0 = gq0 + (lane >> 2), r1 = r0 + 8;
            float tm0 = -CUDART_INF_F, tm1 = -CUDART_INF_F;
            #pragma unroll
            for (int j = 0; j < 8; j++) {
                int cc = kb + j * 8 + ((lane & 3) << 1);
                float v0 = sacc[j][0] * scale, v1 = sacc[j][1] * scale;
                float v2 = sacc[j][2] * scale, v3 = sacc[j][3] * scale;
                if (diag) {
                    if (cc     > r0) v0 = -CUDART_INF_F;
                    if (cc + 1 > r0) v1 = -CUDART_INF_F;
                    if (cc     > r1) v2 = -CUDART_INF_F;
                    if (cc + 1 > r1) v3 = -CUDART_INF_F;
                }
                sacc[j][0] = v0; sacc[j][1] = v1; sacc[j][2] = v2; sacc[j][3] = v3;
                tm0 = fmaxf(tm0, fmaxf(v0, v1));
                tm1 = fmaxf(tm1, fmaxf(v2, v3));
            }
            tm0 = fmaxf(tm0, __shfl_xor_sync(0xffffffffu, tm0, 1));
            tm0 = fmaxf(tm0, __shfl_xor_sync(0xffffffffu, tm0, 2));
            tm1 = fmaxf(tm1, __shfl_xor_sync(0xffffffffu, tm1, 1));
            tm1 = fmaxf(tm1, __shfl_xor_sync(0xffffffffu, tm1, 2));
            float mn0 = fmaxf(m0, tm0), mn1 = fmaxf(m1, tm1);
            float a0 = __expf(m0 - mn0), a1 = __expf(m1 - mn1);
            float rs0 = 0.f, rs1 = 0.f;
            #pragma unroll
            for (int j = 0; j < 8; j++) {
                float p0 = __expf(sacc[j][0] - mn0);
                float p1 = __expf(sacc[j][1] - mn0);
                float p2 = __expf(sacc[j][2] - mn1);
                float p3 = __expf(sacc[j][3] - mn1);
                sacc[j][0] = p0; sacc[j][1] = p1; sacc[j][2] = p2; sacc[j][3] = p3;
                rs0 += p0 + p1; rs1 += p2 + p3;
            }
            rs0 += __shfl_xor_sync(0xffffffffu, rs0, 1);
            rs0 += __shfl_xor_sync(0xffffffffu, rs0, 2);
            rs1 += __shfl_xor_sync(0xffffffffu, rs1, 1);
            rs1 += __shfl_xor_sync(0xffffffffu, rs1, 2);
            l0 = l0 * a0 + rs0; l1 = l1 * a1 + rs1;
            m0 = mn0; m1 = mn1;
            #pragma unroll
            for (int j = 0; j < 16; j++) {
                oacc[j][0] *= a0; oacc[j][1] *= a0;
                oacc[j][2] *= a1; oacc[j][3] *= a1;
            }

            uint32_t ph[4][4], pl[4][4];
            #pragma unroll
            for (int c = 0; c < 4; c++) {
                ph[c][0] = pack_hi(sacc[2*c][0],   sacc[2*c][1]);
                pl[c][0] = pack_lo(sacc[2*c][0],   sacc[2*c][1],   ph[c][0]);
                ph[c][1] = pack_hi(sacc[2*c][2],   sacc[2*c][3]);
                pl[c][1] = pack_lo(sacc[2*c][2],   sacc[2*c][3],   ph[c][1]);
                ph[c][2] = pack_hi(sacc[2*c+1][0], sacc[2*c+1][1]);
                pl[c][2] = pack_lo(sacc[2*c+1][0], sacc[2*c+1][1], ph[c][2]);
                ph[c][3] = pack_hi(sacc[2*c+1][2], sacc[2*c+1][3]);
                pl[c][3] = pack_lo(sacc[2*c+1][2], sacc[2*c+1][3], ph[c][3]);
            }

            const int vrow = ((lane >> 3) & 1) * 8 + (lane & 7);
            const int vcol = (lane >> 4) << 3;
            #pragma unroll
            for (int c = 0; c < 4; c++) {
                #pragma unroll
                for (int dt = 0; dt < 8; dt++) {
                    uint32_t bv[4];
                    uint32_t ad = sb + 2u * (uint32_t)(st + FL_VH + (c * 16 + vrow) * SQ + dt * 16 + vcol);
                    ldmx4t(bv[0], bv[1], bv[2], bv[3], ad);
                    mma16816(oacc[2*dt],   ph[c], bv);
                    mma16816(oacc[2*dt+1], ph[c], bv + 2);
                    mma16816(oacc[2*dt],   pl[c], bv);
                    mma16816(oacc[2*dt+1], pl[c], bv + 2);
                }
                #pragma unroll
                for (int dt = 0; dt < 8; dt++) {
                    uint32_t bv[4];
                    uint32_t ad = sb + 2u * (uint32_t)(st + FL_VL + (c * 16 + vrow) * SQ + dt * 16 + vcol);
                    ldmx4t(bv[0], bv[1], bv[2], bv[3], ad);
                    mma16816(oacc[2*dt],   ph[c], bv);
                    mma16816(oacc[2*dt+1], ph[c], bv + 2);
                }
            }
        }
        __syncthreads();
        s ^= 1;
    }

    float inv0 = 1.0f / l0, inv1 = 1.0f / l1;
    size_t grow0 = (rowQ + wq + (lane >> 2)) * C_;
    size_t grow1 = grow0 + 8 * C_;
    #pragma unroll
    for (int j = 0; j < 16; j++) {
        int col = colH + j * 8 + ((lane & 3) << 1);
        float f0 = oacc[j][0] * inv0, f1 = oacc[j][1] * inv0;
        float f2 = oacc[j][2] * inv1, f3 = oacc[j][3] * inv1;
        uint32_t h0 = pack_hi(f0, f1), h1 = pack_hi(f2, f3);
        *(uint32_t*)&oh[grow0 + col] = h0;
        *(uint32_t*)&ol[grow0 + col] = pack_lo(f0, f1, h0);
        *(uint32_t*)&oh[grow1 + col] = h1;
        *(uint32_t*)&ol[grow1 + col] = pack_lo(f2, f3, h1);
    }
}

// ---------------------------------------------------------------------------
extern "C" void kernel_launch(void* const* d_in, const int* in_sizes, int n_in,
                              void* d_out, int out_size)
{
    (void)in_sizes; (void)n_in; (void)out_size;
    const float* x  = (const float*)d_in[0];
    const float* cs = (const float*)d_in[1];
    const float* sn = (const float*)d_in[2];
    const float* Ws[4] = { (const float*)d_in[3], (const float*)d_in[4],
                           (const float*)d_in[5], (const float*)d_in[6] };
    float* out = (float*)d_out;

    float *q, *k;
    __nv_bfloat16 *xh, *xl, *qh, *ql, *kh, *kl, *vh, *vl, *oh, *ol, *wh, *wl;
    cudaGetSymbolAddress((void**)&q,  g_q);
    cudaGetSymbolAddress((void**)&k,  g_k);
    cudaGetSymbolAddress((void**)&xh, g_xh);
    cudaGetSymbolAddress((void**)&xl, g_xl);
    cudaGetSymbolAddress((void**)&qh, g_qh);
    cudaGetSymbolAddress((void**)&ql, g_ql);
    cudaGetSymbolAddress((void**)&kh, g_kh);
    cudaGetSymbolAddress((void**)&kl, g_kl);
    cudaGetSymbolAddress((void**)&vh, g_vh);
    cudaGetSymbolAddress((void**)&vl, g_vl);
    cudaGetSymbolAddress((void**)&oh, g_oh);
    cudaGetSymbolAddress((void**)&ol, g_ol);
    cudaGetSymbolAddress((void**)&wh, g_wh);
    cudaGetSymbolAddress((void**)&wl, g_wl);

    cudaFuncSetAttribute(bgemm2<0>, cudaFuncAttributeMaxDynamicSharedMemorySize, G_SMEM);
    cudaFuncSetAttribute(bgemm2<1>, cudaFuncAttributeMaxDynamicSharedMemorySize, G_SMEM);
    cudaFuncSetAttribute(flash_bf16, cudaFuncAttributeMaxDynamicSharedMemorySize, FLASH_SMEM);

    const int nx4 = (M_ * C_) / 4;
    const int nw4 = (C_ * C_) / 4;
    split_f32<<<nx4/256, 256>>>((const float4*)x, (uint2*)xh, (uint2*)xl, nx4);
    for (int w = 0; w < 4; w++)
        split_f32<<<nw4/256, 256>>>((const float4*)Ws[w],
                                    (uint2*)(wh + (size_t)w * C_ * C_),
                                    (uint2*)(wl + (size_t)w * C_ * C_), nw4);

    dim3 gemmGrid(C_/256, M_/128);   // (8, 32)
    bgemm2<0><<<gemmGrid, 256, G_SMEM>>>(xh, xl, wh + 0*(size_t)C_*C_, wl + 0*(size_t)C_*C_, q,   nullptr, nullptr, M_, C_, C_);
    bgemm2<0><<<gemmGrid, 256, G_SMEM>>>(xh, xl, wh + 1*(size_t)C_*C_, wl + 1*(size_t)C_*C_, k,   nullptr, nullptr, M_, C_, C_);
    bgemm2<1><<<gemmGrid, 256, G_SMEM>>>(xh, xl, wh + 2*(size_t)C_*C_, wl + 2*(size_t)C_*C_, nullptr, vh, vl,  M_, C_, C_);

    rmsnorm_rope_bf16<<<(B_*T_*H_)/8, 256>>>(q, k, cs, sn, qh, ql, kh, kl);

    flash_bf16<<<dim3(T_/128, B_*H_), 256, FLASH_SMEM>>>(qh, ql, kh, kl, vh, vl, oh, ol);

    bgemm2<0><<<gemmGrid, 256, G_SMEM>>>(oh, ol, wh + 3*(size_t)C_*C_, wl + 3*(size_t)C_*C_, out, nullptr, nullptr, M_, C_, C_);
}

// round 6
// speedup vs baseline: 3.2812x; 1.0159x over previous
#include <cuda_runtime.h>
#include <cuda_bf16.h>
#include <math_constants.h>
#include <cstdint>

#define B_ 2
#define T_ 2048
#define C_ 2048
#define H_ 16
#define D_ 128
#define M_ (B_*T_)   // 4096 rows

// ---------------- scratch (static device globals) ----------------
__device__ float g_q[(size_t)M_ * C_];
__device__ float g_k[(size_t)M_ * C_];
__device__ __nv_bfloat16 g_xh[(size_t)M_ * C_];
__device__ __nv_bfloat16 g_xl[(size_t)M_ * C_];
__device__ __nv_bfloat16 g_qh[(size_t)M_ * C_];
__device__ __nv_bfloat16 g_ql[(size_t)M_ * C_];
__device__ __nv_bfloat16 g_kh[(size_t)M_ * C_];
__device__ __nv_bfloat16 g_kl[(size_t)M_ * C_];
__device__ __nv_bfloat16 g_vh[(size_t)M_ * C_];
__device__ __nv_bfloat16 g_vl[(size_t)M_ * C_];
__device__ __nv_bfloat16 g_oh[(size_t)M_ * C_];
__device__ __nv_bfloat16 g_ol[(size_t)M_ * C_];
__device__ __nv_bfloat16 g_wh[4][(size_t)C_ * C_];
__device__ __nv_bfloat16 g_wl[4][(size_t)C_ * C_];

union BU { __nv_bfloat162 b; uint32_t u; };

__device__ __forceinline__ uint32_t pack_hi(float x, float y) {
    BU u; u.b = __floats2bfloat162_rn(x, y); return u.u;
}
__device__ __forceinline__ uint32_t pack_lo(float x, float y, uint32_t hi) {
    BU h; h.u = hi;
    BU u; u.b = __floats2bfloat162_rn(x - __bfloat162float(h.b.x),
                                      y - __bfloat162float(h.b.y));
    return u.u;
}

// ---------------------------------------------------------------------------
// fp32 -> bf16 hi/lo split
// ---------------------------------------------------------------------------
__global__ __launch_bounds__(256) void split_f32(
    const float4* __restrict__ src, uint2* __restrict__ hi, uint2* __restrict__ lo, int n4)
{
    int i = blockIdx.x * blockDim.x + threadIdx.x;
    if (i >= n4) return;
    float4 v = src[i];
    uint32_t h0 = pack_hi(v.x, v.y), h1 = pack_hi(v.z, v.w);
    uint32_t l0 = pack_lo(v.x, v.y, h0), l1 = pack_lo(v.z, v.w, h1);
    hi[i] = make_uint2(h0, h1);
    lo[i] = make_uint2(l0, l1);
}

// ---------------------------------------------------------------------------
// primitives
// ---------------------------------------------------------------------------
__device__ __forceinline__ void ldmx4(uint32_t &r0, uint32_t &r1, uint32_t &r2, uint32_t &r3, uint32_t addr) {
    asm volatile("ldmatrix.sync.aligned.m8n8.x4.shared.b16 {%0,%1,%2,%3}, [%4];"
                 : "=r"(r0), "=r"(r1), "=r"(r2), "=r"(r3) : "r"(addr));
}
__device__ __forceinline__ void ldmx4t(uint32_t &r0, uint32_t &r1, uint32_t &r2, uint32_t &r3, uint32_t addr) {
    asm volatile("ldmatrix.sync.aligned.m8n8.x4.trans.shared.b16 {%0,%1,%2,%3}, [%4];"
                 : "=r"(r0), "=r"(r1), "=r"(r2), "=r"(r3) : "r"(addr));
}
__device__ __forceinline__ void mma16816(float* d, const uint32_t* a, const uint32_t* b) {
    asm volatile("mma.sync.aligned.m16n8k16.row.col.f32.bf16.bf16.f32 "
                 "{%0,%1,%2,%3},{%4,%5,%6,%7},{%8,%9},{%0,%1,%2,%3};"
                 : "+f"(d[0]), "+f"(d[1]), "+f"(d[2]), "+f"(d[3])
                 : "r"(a[0]), "r"(a[1]), "r"(a[2]), "r"(a[3]), "r"(b[0]), "r"(b[1]));
}
__device__ __forceinline__ void cp16(uint32_t saddr, const void* g) {
    asm volatile("cp.async.cg.shared.global [%0], [%1], 16;" :: "r"(saddr), "l"(g));
}
// SW64 swizzle for 64-byte rows
__device__ __forceinline__ uint32_t swz64(uint32_t off) { return off ^ ((off >> 3) & 0x30); }

// ---------------------------------------------------------------------------
// bf16-split tensor-core GEMM:  C[M,N] = A[M,K] @ B[N,K]^T  (3-term hi/lo)
// CTA tile 128x128, BK=32, 8 warps with 32x64 warp tiles, 3-stage cp.async,
// 2 CTAs/SM (96KB smem, <=128 regs).
// OMODE 0: fp32 out.  OMODE 1: bf16 hi/lo out.
// ---------------------------------------------------------------------------
#define G3_SUB 8192                      // one term subtile: 128 rows x 64B
#define G3_STAGE (4*G3_SUB)              // 32768 B (Ah, Al, Bh, Bl)
#define G3_SMEM (3*G3_STAGE)             // 98304 B

template<int OMODE>
__global__ __launch_bounds__(256, 2) void bgemm3(
    const __nv_bfloat16* __restrict__ Ah, const __nv_bfloat16* __restrict__ Al,
    const __nv_bfloat16* __restrict__ Bh, const __nv_bfloat16* __restrict__ Bl,
    float* __restrict__ Cc, __nv_bfloat16* __restrict__ Ch, __nv_bfloat16* __restrict__ Cl,
    int Mm, int Nn, int K)
{
    extern __shared__ __align__(1024) char smg[];
    const int tid = threadIdx.x, lane = tid & 31, wid = tid >> 5;
    const int warp_m = wid & 3;          // 4 -> 32 rows each
    const int warp_n = wid >> 2;         // 2 -> 64 cols each
    const int bm = blockIdx.y, bn = blockIdx.x;
    const uint32_t sb = (uint32_t)__cvta_generic_to_shared(smg);

    float acc[2][8][4];
    #pragma unroll
    for (int i = 0; i < 2; i++)
        #pragma unroll
        for (int j = 0; j < 8; j++)
            #pragma unroll
            for (int e = 0; e < 4; e++) acc[i][j][e] = 0.f;

    const __nv_bfloat16* srcs[4] = { Ah, Al, Bh, Bl };

    auto issue = [&](int s, int k0) {
        const uint32_t st = sb + s * G3_STAGE;
        // 4 subtiles x 128 rows x 4 chunks = 2048 chunks, 8 per thread
        #pragma unroll
        for (int it = 0; it < 8; it++) {
            int j   = tid + it * 256;
            int sub = j >> 9;            // 0..3
            int cid = j & 511;
            int r   = cid >> 2;          // 0..127
            int ch  = cid & 3;
            int grow = (sub < 2 ? bm : bn) * 128 + r;
            const __nv_bfloat16* g = srcs[sub] + (size_t)grow * K + k0 + ch * 8;
            cp16(st + sub * G3_SUB + swz64((uint32_t)(r * 64 + ch * 16)), g);
        }
        asm volatile("cp.async.commit_group;");
    };

    const int NS = K / 32;   // 64
    issue(0, 0);
    issue(1, 32);

    const int mlane = lane & 15;
    const int aoff  = (lane >> 4) << 3;
    const int nlane = (lane & 7) + ((lane >> 4) << 3);
    const int klBo  = ((lane >> 3) & 1) << 3;

    for (int i = 0; i < NS; i++) {
        if (i == NS - 1) { asm volatile("cp.async.wait_group 0;"); }
        else             { asm volatile("cp.async.wait_group 1;"); }
        __syncthreads();
        if (i + 2 < NS) issue((i + 2) % 3, (i + 2) * 32);

        const uint32_t st = sb + (i % 3) * G3_STAGE;
        #pragma unroll
        for (int kk = 0; kk < 32; kk += 16) {
            uint32_t ah[2][4], al[2][4], b[8][2];
            #pragma unroll
            for (int t = 0; t < 2; t++) {
                uint32_t rb = (uint32_t)((warp_m * 32 + t * 16 + mlane) * 64 + (kk + aoff) * 2);
                ldmx4(ah[t][0], ah[t][1], ah[t][2], ah[t][3], st + 0 * G3_SUB + swz64(rb));
                ldmx4(al[t][0], al[t][1], al[t][2], al[t][3], st + 1 * G3_SUB + swz64(rb));
            }
            #pragma unroll
            for (int jt = 0; jt < 4; jt++) {
                uint32_t rb = (uint32_t)((warp_n * 64 + jt * 16 + nlane) * 64 + (kk + klBo) * 2);
                ldmx4(b[2*jt][0], b[2*jt][1], b[2*jt+1][0], b[2*jt+1][1], st + 2 * G3_SUB + swz64(rb));
            }
            #pragma unroll
            for (int t = 0; t < 2; t++)
                #pragma unroll
                for (int j = 0; j < 8; j++) mma16816(acc[t][j], ah[t], b[j]);   // hi*hi
            #pragma unroll
            for (int t = 0; t < 2; t++)
                #pragma unroll
                for (int j = 0; j < 8; j++) mma16816(acc[t][j], al[t], b[j]);   // lo*hi
            #pragma unroll
            for (int jt = 0; jt < 4; jt++) {
                uint32_t rb = (uint32_t)((warp_n * 64 + jt * 16 + nlane) * 64 + (kk + klBo) * 2);
                ldmx4(b[2*jt][0], b[2*jt][1], b[2*jt+1][0], b[2*jt+1][1], st + 3 * G3_SUB + swz64(rb));
            }
            #pragma unroll
            for (int t = 0; t < 2; t++)
                #pragma unroll
                for (int j = 0; j < 8; j++) mma16816(acc[t][j], ah[t], b[j]);   // hi*lo
        }
        __syncthreads();
    }

    // epilogue
    #pragma unroll
    for (int t = 0; t < 2; t++) {
        int row = bm * 128 + warp_m * 32 + t * 16 + (lane >> 2);
        #pragma unroll
        for (int j = 0; j < 8; j++) {
            int col = bn * 128 + warp_n * 64 + j * 8 + ((lane & 3) << 1);
            if (OMODE == 0) {
                *(float2*)&Cc[(size_t)row * Nn + col]       = make_float2(acc[t][j][0], acc[t][j][1]);
                *(float2*)&Cc[(size_t)(row + 8) * Nn + col] = make_float2(acc[t][j][2], acc[t][j][3]);
            } else {
                uint32_t h0 = pack_hi(acc[t][j][0], acc[t][j][1]);
                uint32_t l0 = pack_lo(acc[t][j][0], acc[t][j][1], h0);
                uint32_t h1 = pack_hi(acc[t][j][2], acc[t][j][3]);
                uint32_t l1 = pack_lo(acc[t][j][2], acc[t][j][3], h1);
                *(uint32_t*)&Ch[(size_t)row * Nn + col]       = h0;
                *(uint32_t*)&Cl[(size_t)row * Nn + col]       = l0;
                *(uint32_t*)&Ch[(size_t)(row + 8) * Nn + col] = h1;
                *(uint32_t*)&Cl[(size_t)(row + 8) * Nn + col] = l1;
            }
        }
    }
}

// ---------------------------------------------------------------------------
// Fused per-head RMSNorm + RoPE; reads fp32 q,k; writes bf16 hi/lo.
// ---------------------------------------------------------------------------
__global__ __launch_bounds__(256) void rmsnorm_rope_bf16(
    const float* __restrict__ q, const float* __restrict__ k,
    const float* __restrict__ cs, const float* __restrict__ sn,
    __nv_bfloat16* __restrict__ qh, __nv_bfloat16* __restrict__ ql,
    __nv_bfloat16* __restrict__ kh, __nv_bfloat16* __restrict__ kl)
{
    int gw   = (blockIdx.x * blockDim.x + threadIdx.x) >> 5;
    int lane = threadIdx.x & 31;
    if (gw >= B_ * T_ * H_) return;
    int h  = gw % H_;
    int bt = gw / H_;
    int t  = bt % T_;

    const float c0 = cs[t*64 + lane], c1 = cs[t*64 + lane + 32];
    const float s0 = sn[t*64 + lane], s1 = sn[t*64 + lane + 32];

    #pragma unroll
    for (int w = 0; w < 2; w++) {
        const float* base = (w ? k : q) + (size_t)bt * C_ + h * D_;
        __nv_bfloat16* oh = (w ? kh : qh) + (size_t)bt * C_ + h * D_;
        __nv_bfloat16* ol = (w ? kl : ql) + (size_t)bt * C_ + h * D_;
        float x0 = base[lane], x1 = base[lane+32], x2 = base[lane+64], x3 = base[lane+96];
        float ss = x0*x0 + x1*x1 + x2*x2 + x3*x3;
        #pragma unroll
        for (int m = 16; m; m >>= 1) ss += __shfl_xor_sync(0xffffffffu, ss, m);
        float r = rsqrtf(ss * (1.0f/128.0f) + 1.1920929e-7f);
        x0 *= r; x1 *= r; x2 *= r; x3 *= r;
        float y0 =  x0*c0 + x2*s0;
        float y1 =  x1*c1 + x3*s1;
        float y2 = -x0*s0 + x2*c0;
        float y3 = -x1*s1 + x3*c1;
        __nv_bfloat16 h0 = __float2bfloat16(y0);
        __nv_bfloat16 h1 = __float2bfloat16(y1);
        __nv_bfloat16 h2 = __float2bfloat16(y2);
        __nv_bfloat16 h3 = __float2bfloat16(y3);
        oh[lane] = h0; oh[lane+32] = h1; oh[lane+64] = h2; oh[lane+96] = h3;
        ol[lane]    = __float2bfloat16(y0 - __bfloat162float(h0));
        ol[lane+32] = __float2bfloat16(y1 - __bfloat162float(h1));
        ol[lane+64] = __float2bfloat16(y2 - __bfloat162float(h2));
        ol[lane+96] = __float2bfloat16(y3 - __bfloat162float(h3));
    }
}

// ---------------------------------------------------------------------------
// Tensor-core flash attention (causal), bf16 hi/lo 3-term, fp32 accum.
// Q fragments held in registers; KV double-buffered (139 KB smem).
// ---------------------------------------------------------------------------
#define SQ 136
#define FL_STAGE (4*64*SQ)               // 34816 elems: Kh, Kl, Vh, Vl (64 rows each)
#define FL_KH 0
#define FL_KL (64*SQ)
#define FL_VH (128*SQ)
#define FL_VL (192*SQ)
#define FLASH_SMEM (2*FL_STAGE*2)        // 139264 bytes

__global__ __launch_bounds__(256, 1) void flash_bf16(
    const __nv_bfloat16* __restrict__ qh, const __nv_bfloat16* __restrict__ ql,
    const __nv_bfloat16* __restrict__ kh, const __nv_bfloat16* __restrict__ kl,
    const __nv_bfloat16* __restrict__ vh, const __nv_bfloat16* __restrict__ vl,
    __nv_bfloat16* __restrict__ oh, __nv_bfloat16* __restrict__ ol)
{
    extern __shared__ __nv_bfloat16 smf[];
    const int tid = threadIdx.x, lane = tid & 31, wid = tid >> 5;
    const int qb = gridDim.x - 1 - blockIdx.x;
    const int b  = blockIdx.y >> 4, h = blockIdx.y & 15;
    const uint32_t sb = (uint32_t)__cvta_generic_to_shared(smf);
    const size_t rowQ = (size_t)b * T_ + (size_t)qb * 128;
    const int colH = h * D_;

    const int wq = wid * 16;
    const int gq0 = qb * 128 + wq;
    const int mlane = lane & 15;
    const int aoff  = (lane >> 4) << 3;
    const int nlane = (lane & 7) + ((lane >> 4) << 3);
    const int klB   = ((lane >> 3) & 1) << 3;

    // ---- stage Q through smem (uses KV buffer region), extract to registers ----
    // Q hi at [0, 128*SQ), Q lo at [128*SQ, 256*SQ)  (= exactly FL_STAGE elems)
    #pragma unroll
    for (int it = 0; it < 8; it++) {
        int idx = tid + it * 256;
        int r = idx >> 4, c = (idx & 15) << 3;
        size_t g = (rowQ + r) * C_ + colH + c;
        cp16(sb + 2u * (uint32_t)(r * SQ + c), qh + g);
        cp16(sb + 2u * (uint32_t)(128 * SQ + r * SQ + c), ql + g);
    }
    asm volatile("cp.async.commit_group;");
    asm volatile("cp.async.wait_group 0;");
    __syncthreads();

    uint32_t qfh[8][4], qfl[8][4];
    #pragma unroll
    for (int c = 0; c < 8; c++) {
        uint32_t ad = sb + 2u * (uint32_t)((wq + mlane) * SQ + c * 16 + aoff);
        ldmx4(qfh[c][0], qfh[c][1], qfh[c][2], qfh[c][3], ad);
        ldmx4(qfl[c][0], qfl[c][1], qfl[c][2], qfl[c][3], ad + 2u * (uint32_t)(128 * SQ));
    }
    __syncthreads();   // everyone done reading Q before KV overwrites

    auto issueKV = [&](int s, int kt) {
        uint32_t st = s * FL_STAGE;
        #pragma unroll
        for (int it = 0; it < 4; it++) {
            int idx = tid + it * 256;
            int r = idx >> 4, c = (idx & 15) << 3;
            size_t g = ((size_t)b * T_ + (size_t)kt * 64 + r) * C_ + colH + c;
            uint32_t so = (uint32_t)(st + r * SQ + c);
            cp16(sb + 2u * (so + FL_KH), kh + g);
            cp16(sb + 2u * (so + FL_KL), kl + g);
            cp16(sb + 2u * (so + FL_VH), vh + g);
            cp16(sb + 2u * (so + FL_VL), vl + g);
        }
        asm volatile("cp.async.commit_group;");
    };

    issueKV(0, 0);

    const int nkt = 2 * qb + 2;
    const float scale = 0.088388347648318447f;

    float m0 = -CUDART_INF_F, m1 = -CUDART_INF_F, l0 = 0.f, l1 = 0.f;
    float oacc[16][4];
    #pragma unroll
    for (int j = 0; j < 16; j++)
        #pragma unroll
        for (int e = 0; e < 4; e++) oacc[j][e] = 0.f;

    int s = 0;
    for (int kt = 0; kt < nkt; kt++) {
        if (kt + 1 < nkt) {
            issueKV(s ^ 1, kt + 1);
            asm volatile("cp.async.wait_group 1;");
        } else {
            asm volatile("cp.async.wait_group 0;");
        }
        __syncthreads();

        const int kb = kt * 64;
        if (kb <= gq0 + 15) {
            const uint32_t st = s * FL_STAGE;

            float sacc[8][4];
            #pragma unroll
            for (int j = 0; j < 8; j++)
                #pragma unroll
                for (int e = 0; e < 4; e++) sacc[j][e] = 0.f;

            #pragma unroll
            for (int c = 0; c < 8; c++) {
                uint32_t bh2[8][2];
                #pragma unroll
                for (int jt = 0; jt < 4; jt++) {
                    uint32_t ad = sb + 2u * (uint32_t)(st + FL_KH + (jt * 16 + nlane) * SQ + c * 16 + klB);
                    ldmx4(bh2[2*jt][0], bh2[2*jt][1], bh2[2*jt+1][0], bh2[2*jt+1][1], ad);
                }
                #pragma unroll
                for (int j = 0; j < 8; j++) mma16816(sacc[j], qfh[c], bh2[j]);
                #pragma unroll
                for (int j = 0; j < 8; j++) mma16816(sacc[j], qfl[c], bh2[j]);
                #pragma unroll
                for (int jt = 0; jt < 4; jt++) {
                    uint32_t ad = sb + 2u * (uint32_t)(st + FL_KL + (jt * 16 + nlane) * SQ + c * 16 + klB);
                    ldmx4(bh2[2*jt][0], bh2[2*jt][1], bh2[2*jt+1][0], bh2[2*jt+1][1], ad);
                }
                #pragma unroll
                for (int j = 0; j < 8; j++) mma16816(sacc[j], qfh[c], bh2[j]);
            }

            const bool diag = (kb + 63 > gq0);
            const int r0 = gq0 + (lane >> 2), r1 = r0 + 8;
            float tm0 = -CUDART_INF_F, tm1 = -CUDART_INF_F;
            #pragma unroll
            for (int j = 0; j < 8; j++) {
                int cc = kb + j * 8 + ((lane & 3) << 1);
                float v0 = sacc[j][0] * scale, v1 = sacc[j][1] * scale;
                float v2 = sacc[j][2] * scale, v3 = sacc[j][3] * scale;
                if (diag) {
                    if (cc     > r0) v0 = -CUDART_INF_F;
                    if (cc + 1 > r0) v1 = -CUDART_INF_F;
                    if (cc     > r1) v2 = -CUDART_INF_F;
                    if (cc + 1 > r1) v3 = -CUDART_INF_F;
                }
                sacc[j][0] = v0; sacc[j][1] = v1; sacc[j][2] = v2; sacc[j][3] = v3;
                tm0 = fmaxf(tm0, fmaxf(v0, v1));
                tm1 = fmaxf(tm1, fmaxf(v2, v3));
            }
            tm0 = fmaxf(tm0, __shfl_xor_sync(0xffffffffu, tm0, 1));
            tm0 = fmaxf(tm0, __shfl_xor_sync(0xffffffffu, tm0, 2));
            tm1 = fmaxf(tm1, __shfl_xor_sync(0xffffffffu, tm1, 1));
            tm1 = fmaxf(tm1, __shfl_xor_sync(0xffffffffu, tm1, 2));
            float mn0 = fmaxf(m0, tm0), mn1 = fmaxf(m1, tm1);
            float a0 = __expf(m0 - mn0), a1 = __expf(m1 - mn1);
            float rs0 = 0.f, rs1 = 0.f;
            #pragma unroll
            for (int j = 0; j < 8; j++) {
                float p0 = __expf(sacc[j][0] - mn0);
                float p1 = __expf(sacc[j][1] - mn0);
                float p2 = __expf(sacc[j][2] - mn1);
                float p3 = __expf(sacc[j][3] - mn1);
                sacc[j][0] = p0; sacc[j][1] = p1; sacc[j][2] = p2; sacc[j][3] = p3;
                rs0 += p0 + p1; rs1 += p2 + p3;
            }
            rs0 += __shfl_xor_sync(0xffffffffu, rs0, 1);
            rs0 += __shfl_xor_sync(0xffffffffu, rs0, 2);
            rs1 += __shfl_xor_sync(0xffffffffu, rs1, 1);
            rs1 += __shfl_xor_sync(0xffffffffu, rs1, 2);
            l0 = l0 * a0 + rs0; l1 = l1 * a1 + rs1;
            m0 = mn0; m1 = mn1;
            #pragma unroll
            for (int j = 0; j < 16; j++) {
                oacc[j][0] *= a0; oacc[j][1] *= a0;
                oacc[j][2] *= a1; oacc[j][3] *= a1;
            }

            uint32_t ph[4][4], pl[4][4];
            #pragma unroll
            for (int c = 0; c < 4; c++) {
                ph[c][0] = pack_hi(sacc[2*c][0],   sacc[2*c][1]);
                pl[c][0] = pack_lo(sacc[2*c][0],   sacc[2*c][1],   ph[c][0]);
                ph[c][1] = pack_hi(sacc[2*c][2],   sacc[2*c][3]);
                pl[c][1] = pack_lo(sacc[2*c][2],   sacc[2*c][3],   ph[c][1]);
                ph[c][2] = pack_hi(sacc[2*c+1][0], sacc[2*c+1][1]);
                pl[c][2] = pack_lo(sacc[2*c+1][0], sacc[2*c+1][1], ph[c][2]);
                ph[c][3] = pack_hi(sacc[2*c+1][2], sacc[2*c+1][3]);
                pl[c][3] = pack_lo(sacc[2*c+1][2], sacc[2*c+1][3], ph[c][3]);
            }

            const int vrow = ((lane >> 3) & 1) * 8 + (lane & 7);
            const int vcol = (lane >> 4) << 3;
            #pragma unroll
            for (int c = 0; c < 4; c++) {
                #pragma unroll
                for (int dt = 0; dt < 8; dt++) {
                    uint32_t bv[4];
                    uint32_t ad = sb + 2u * (uint32_t)(st + FL_VH + (c * 16 + vrow) * SQ + dt * 16 + vcol);
                    ldmx4t(bv[0], bv[1], bv[2], bv[3], ad);
                    mma16816(oacc[2*dt],   ph[c], bv);
                    mma16816(oacc[2*dt+1], ph[c], bv + 2);
                    mma16816(oacc[2*dt],   pl[c], bv);
                    mma16816(oacc[2*dt+1], pl[c], bv + 2);
                }
                #pragma unroll
                for (int dt = 0; dt < 8; dt++) {
                    uint32_t bv[4];
                    uint32_t ad = sb + 2u * (uint32_t)(st + FL_VL + (c * 16 + vrow) * SQ + dt * 16 + vcol);
                    ldmx4t(bv[0], bv[1], bv[2], bv[3], ad);
                    mma16816(oacc[2*dt],   ph[c], bv);
                    mma16816(oacc[2*dt+1], ph[c], bv + 2);
                }
            }
        }
        __syncthreads();
        s ^= 1;
    }

    float inv0 = 1.0f / l0, inv1 = 1.0f / l1;
    size_t grow0 = (rowQ + wq + (lane >> 2)) * C_;
    size_t grow1 = grow0 + 8 * C_;
    #pragma unroll
    for (int j = 0; j < 16; j++) {
        int col = colH + j * 8 + ((lane & 3) << 1);
        float f0 = oacc[j][0] * inv0, f1 = oacc[j][1] * inv0;
        float f2 = oacc[j][2] * inv1, f3 = oacc[j][3] * inv1;
        uint32_t h0 = pack_hi(f0, f1), h1 = pack_hi(f2, f3);
        *(uint32_t*)&oh[grow0 + col] = h0;
        *(uint32_t*)&ol[grow0 + col] = pack_lo(f0, f1, h0);
        *(uint32_t*)&oh[grow1 + col] = h1;
        *(uint32_t*)&ol[grow1 + col] = pack_lo(f2, f3, h1);
    }
}

// ---------------------------------------------------------------------------
extern "C" void kernel_launch(void* const* d_in, const int* in_sizes, int n_in,
                              void* d_out, int out_size)
{
    (void)in_sizes; (void)n_in; (void)out_size;
    const float* x  = (const float*)d_in[0];
    const float* cs = (const float*)d_in[1];
    const float* sn = (const float*)d_in[2];
    const float* Ws[4] = { (const float*)d_in[3], (const float*)d_in[4],
                           (const float*)d_in[5], (const float*)d_in[6] };
    float* out = (float*)d_out;

    float *q, *k;
    __nv_bfloat16 *xh, *xl, *qh, *ql, *kh, *kl, *vh, *vl, *oh, *ol, *wh, *wl;
    cudaGetSymbolAddress((void**)&q,  g_q);
    cudaGetSymbolAddress((void**)&k,  g_k);
    cudaGetSymbolAddress((void**)&xh, g_xh);
    cudaGetSymbolAddress((void**)&xl, g_xl);
    cudaGetSymbolAddress((void**)&qh, g_qh);
    cudaGetSymbolAddress((void**)&ql, g_ql);
    cudaGetSymbolAddress((void**)&kh, g_kh);
    cudaGetSymbolAddress((void**)&kl, g_kl);
    cudaGetSymbolAddress((void**)&vh, g_vh);
    cudaGetSymbolAddress((void**)&vl, g_vl);
    cudaGetSymbolAddress((void**)&oh, g_oh);
    cudaGetSymbolAddress((void**)&ol, g_ol);
    cudaGetSymbolAddress((void**)&wh, g_wh);
    cudaGetSymbolAddress((void**)&wl, g_wl);

    cudaFuncSetAttribute(bgemm3<0>, cudaFuncAttributeMaxDynamicSharedMemorySize, G3_SMEM);
    cudaFuncSetAttribute(bgemm3<1>, cudaFuncAttributeMaxDynamicSharedMemorySize, G3_SMEM);
    cudaFuncSetAttribute(flash_bf16, cudaFuncAttributeMaxDynamicSharedMemorySize, FLASH_SMEM);

    const int nx4 = (M_ * C_) / 4;
    const int nw4 = (C_ * C_) / 4;
    split_f32<<<nx4/256, 256>>>((const float4*)x, (uint2*)xh, (uint2*)xl, nx4);
    for (int w = 0; w < 4; w++)
        split_f32<<<nw4/256, 256>>>((const float4*)Ws[w],
                                    (uint2*)(wh + (size_t)w * C_ * C_),
                                    (uint2*)(wl + (size_t)w * C_ * C_), nw4);

    dim3 gemmGrid(C_/128, M_/128);   // (16, 32) = 512 CTAs, 2/SM resident
    bgemm3<0><<<gemmGrid, 256, G3_SMEM>>>(xh, xl, wh + 0*(size_t)C_*C_, wl + 0*(size_t)C_*C_, q,   nullptr, nullptr, M_, C_, C_);
    bgemm3<0><<<gemmGrid, 256, G3_SMEM>>>(xh, xl, wh + 1*(size_t)C_*C_, wl + 1*(size_t)C_*C_, k,   nullptr, nullptr, M_, C_, C_);
    bgemm3<1><<<gemmGrid, 256, G3_SMEM>>>(xh, xl, wh + 2*(size_t)C_*C_, wl + 2*(size_t)C_*C_, nullptr, vh, vl,  M_, C_, C_);

    rmsnorm_rope_bf16<<<(B_*T_*H_)/8, 256>>>(q, k, cs, sn, qh, ql, kh, kl);

    flash_bf16<<<dim3(T_/128, B_*H_), 256, FLASH_SMEM>>>(qh, ql, kh, kl, vh, vl, oh, ol);

    bgemm3<0><<<gemmGrid, 256, G3_SMEM>>>(oh, ol, wh + 3*(size_t)C_*C_, wl + 3*(size_t)C_*C_, out, nullptr, nullptr, M_, C_, C_);
}

// round 7
// speedup vs baseline: 3.4560x; 1.0533x over previous
#include <cuda_runtime.h>
#include <cuda_bf16.h>
#include <math_constants.h>
#include <cstdint>

#define B_ 2
#define T_ 2048
#define C_ 2048
#define H_ 16
#define D_ 128
#define M_ (B_*T_)   // 4096 rows

// ---------------- scratch (static device globals) ----------------
__device__ __nv_bfloat16 g_xh[(size_t)M_ * C_];
__device__ __nv_bfloat16 g_xl[(size_t)M_ * C_];
__device__ __nv_bfloat16 g_qh[(size_t)M_ * C_];
__device__ __nv_bfloat16 g_ql[(size_t)M_ * C_];
__device__ __nv_bfloat16 g_kh[(size_t)M_ * C_];
__device__ __nv_bfloat16 g_kl[(size_t)M_ * C_];
__device__ __nv_bfloat16 g_vh[(size_t)M_ * C_];
__device__ __nv_bfloat16 g_vl[(size_t)M_ * C_];
__device__ __nv_bfloat16 g_oh[(size_t)M_ * C_];
__device__ __nv_bfloat16 g_ol[(size_t)M_ * C_];
__device__ __nv_bfloat16 g_wh[4][(size_t)C_ * C_];
__device__ __nv_bfloat16 g_wl[4][(size_t)C_ * C_];

union BU { __nv_bfloat162 b; uint32_t u; };

__device__ __forceinline__ uint32_t pack_hi(float x, float y) {
    BU u; u.b = __floats2bfloat162_rn(x, y); return u.u;
}
__device__ __forceinline__ uint32_t pack_lo(float x, float y, uint32_t hi) {
    BU h; h.u = hi;
    BU u; u.b = __floats2bfloat162_rn(x - __bfloat162float(h.b.x),
                                      y - __bfloat162float(h.b.y));
    return u.u;
}

// ---------------------------------------------------------------------------
// fp32 -> bf16 hi/lo split, all 5 tensors in one launch
// ---------------------------------------------------------------------------
#define NX4 ((M_*C_)/4)
#define NW4 ((C_*C_)/4)

__global__ __launch_bounds__(256) void split_all(
    const float4* __restrict__ x,
    const float4* __restrict__ w0, const float4* __restrict__ w1,
    const float4* __restrict__ w2, const float4* __restrict__ w3,
    uint2* __restrict__ xh, uint2* __restrict__ xl,
    uint2* __restrict__ wh, uint2* __restrict__ wl)
{
    int i = blockIdx.x * blockDim.x + threadIdx.x;
    const float4* src;
    uint2 *ph, *pl;
    int off;
    if (i < NX4) {
        src = x; off = i; ph = xh; pl = xl;
    } else {
        int j = i - NX4;
        int w = j / NW4;
        off = j - w * NW4;
        src = (w == 0) ? w0 : (w == 1) ? w1 : (w == 2) ? w2 : w3;
        ph = wh + (size_t)w * NW4;
        pl = wl + (size_t)w * NW4;
        src = src;
    }
    float4 v = src[off];
    uint32_t h0 = pack_hi(v.x, v.y), h1 = pack_hi(v.z, v.w);
    uint32_t l0 = pack_lo(v.x, v.y, h0), l1 = pack_lo(v.z, v.w, h1);
    ph[off] = make_uint2(h0, h1);
    pl[off] = make_uint2(l0, l1);
}

// ---------------------------------------------------------------------------
// primitives
// ---------------------------------------------------------------------------
__device__ __forceinline__ void ldmx4(uint32_t &r0, uint32_t &r1, uint32_t &r2, uint32_t &r3, uint32_t addr) {
    asm volatile("ldmatrix.sync.aligned.m8n8.x4.shared.b16 {%0,%1,%2,%3}, [%4];"
                 : "=r"(r0), "=r"(r1), "=r"(r2), "=r"(r3) : "r"(addr));
}
__device__ __forceinline__ void ldmx4t(uint32_t &r0, uint32_t &r1, uint32_t &r2, uint32_t &r3, uint32_t addr) {
    asm volatile("ldmatrix.sync.aligned.m8n8.x4.trans.shared.b16 {%0,%1,%2,%3}, [%4];"
                 : "=r"(r0), "=r"(r1), "=r"(r2), "=r"(r3) : "r"(addr));
}
__device__ __forceinline__ void mma16816(float* d, const uint32_t* a, const uint32_t* b) {
    asm volatile("mma.sync.aligned.m16n8k16.row.col.f32.bf16.bf16.f32 "
                 "{%0,%1,%2,%3},{%4,%5,%6,%7},{%8,%9},{%0,%1,%2,%3};"
                 : "+f"(d[0]), "+f"(d[1]), "+f"(d[2]), "+f"(d[3])
                 : "r"(a[0]), "r"(a[1]), "r"(a[2]), "r"(a[3]), "r"(b[0]), "r"(b[1]));
}
__device__ __forceinline__ void cp16(uint32_t saddr, const void* g) {
    asm volatile("cp.async.cg.shared.global [%0], [%1], 16;" :: "r"(saddr), "l"(g));
}
__device__ __forceinline__ uint32_t swz64(uint32_t off) { return off ^ ((off >> 3) & 0x30); }

// ---------------------------------------------------------------------------
// GEMM core geometry: CTA tile 128x128, BK=32, 8 warps (32x64), 3 stages.
// ---------------------------------------------------------------------------
#define G3_SUB 8192
#define G3_STAGE (4*G3_SUB)              // 32768 B
#define G3_SMEM (3*G3_STAGE)             // 98304 B
#define FTS 133                          // fp32 staging stride (epilogue)

// ---------------------------------------------------------------------------
// Fused QKV GEMM + (rmsnorm+RoPE | v split) epilogue.
// grid (48, 32): bn>>4 selects Wq/Wk/Wv, bn&15 = head.
// ---------------------------------------------------------------------------
__global__ __launch_bounds__(256, 2) void qkv_gemm(
    const __nv_bfloat16* __restrict__ xh, const __nv_bfloat16* __restrict__ xl,
    const __nv_bfloat16* __restrict__ wh, const __nv_bfloat16* __restrict__ wl,
    const float* __restrict__ cs, const float* __restrict__ sn,
    __nv_bfloat16* __restrict__ qh, __nv_bfloat16* __restrict__ ql,
    __nv_bfloat16* __restrict__ kh, __nv_bfloat16* __restrict__ kl,
    __nv_bfloat16* __restrict__ vh, __nv_bfloat16* __restrict__ vl)
{
    extern __shared__ __align__(1024) char smg[];
    const int tid = threadIdx.x, lane = tid & 31, wid = tid >> 5;
    const int warp_m = wid & 3;
    const int warp_n = wid >> 2;
    const int bm = blockIdx.y;
    const int kind = blockIdx.x >> 4;          // 0=q 1=k 2=v
    const int lbn  = blockIdx.x & 15;          // head
    const uint32_t sb = (uint32_t)__cvta_generic_to_shared(smg);

    const __nv_bfloat16* Bh = wh + (size_t)kind * C_ * C_;
    const __nv_bfloat16* Bl = wl + (size_t)kind * C_ * C_;

    float acc[2][8][4];
    #pragma unroll
    for (int i = 0; i < 2; i++)
        #pragma unroll
        for (int j = 0; j < 8; j++)
            #pragma unroll
            for (int e = 0; e < 4; e++) acc[i][j][e] = 0.f;

    const __nv_bfloat16* srcs[4] = { xh, xl, Bh, Bl };

    auto issue = [&](int s, int k0) {
        const uint32_t st = sb + s * G3_STAGE;
        #pragma unroll
        for (int it = 0; it < 8; it++) {
            int j   = tid + it * 256;
            int sub = j >> 9;
            int cid = j & 511;
            int r   = cid >> 2;
            int ch  = cid & 3;
            int grow = (sub < 2 ? bm : lbn) * 128 + r;
            const __nv_bfloat16* g = srcs[sub] + (size_t)grow * C_ + k0 + ch * 8;
            cp16(st + sub * G3_SUB + swz64((uint32_t)(r * 64 + ch * 16)), g);
        }
        asm volatile("cp.async.commit_group;");
    };

    const int NS = C_ / 32;   // 64
    issue(0, 0);
    issue(1, 32);

    const int mlane = lane & 15;
    const int aoff  = (lane >> 4) << 3;
    const int nlane = (lane & 7) + ((lane >> 4) << 3);
    const int klBo  = ((lane >> 3) & 1) << 3;

    for (int i = 0; i < NS; i++) {
        if (i == NS - 1) { asm volatile("cp.async.wait_group 0;"); }
        else             { asm volatile("cp.async.wait_group 1;"); }
        __syncthreads();
        if (i + 2 < NS) issue((i + 2) % 3, (i + 2) * 32);

        const uint32_t st = sb + (i % 3) * G3_STAGE;
        #pragma unroll
        for (int kk = 0; kk < 32; kk += 16) {
            uint32_t ah[2][4], al[2][4], b[8][2];
            #pragma unroll
            for (int t = 0; t < 2; t++) {
                uint32_t rb = (uint32_t)((warp_m * 32 + t * 16 + mlane) * 64 + (kk + aoff) * 2);
                ldmx4(ah[t][0], ah[t][1], ah[t][2], ah[t][3], st + 0 * G3_SUB + swz64(rb));
                ldmx4(al[t][0], al[t][1], al[t][2], al[t][3], st + 1 * G3_SUB + swz64(rb));
            }
            #pragma unroll
            for (int jt = 0; jt < 4; jt++) {
                uint32_t rb = (uint32_t)((warp_n * 64 + jt * 16 + nlane) * 64 + (kk + klBo) * 2);
                ldmx4(b[2*jt][0], b[2*jt][1], b[2*jt+1][0], b[2*jt+1][1], st + 2 * G3_SUB + swz64(rb));
            }
            #pragma unroll
            for (int t = 0; t < 2; t++)
                #pragma unroll
                for (int j = 0; j < 8; j++) mma16816(acc[t][j], ah[t], b[j]);
            #pragma unroll
            for (int t = 0; t < 2; t++)
                #pragma unroll
                for (int j = 0; j < 8; j++) mma16816(acc[t][j], al[t], b[j]);
            #pragma unroll
            for (int jt = 0; jt < 4; jt++) {
                uint32_t rb = (uint32_t)((warp_n * 64 + jt * 16 + nlane) * 64 + (kk + klBo) * 2);
                ldmx4(b[2*jt][0], b[2*jt][1], b[2*jt+1][0], b[2*jt+1][1], st + 3 * G3_SUB + swz64(rb));
            }
            #pragma unroll
            for (int t = 0; t < 2; t++)
                #pragma unroll
                for (int j = 0; j < 8; j++) mma16816(acc[t][j], ah[t], b[j]);
        }
        __syncthreads();
    }

    if (kind == 2) {
        // ---- V epilogue: direct bf16 hi/lo ----
        #pragma unroll
        for (int t = 0; t < 2; t++) {
            int row = bm * 128 + warp_m * 32 + t * 16 + (lane >> 2);
            #pragma unroll
            for (int j = 0; j < 8; j++) {
                int col = lbn * 128 + warp_n * 64 + j * 8 + ((lane & 3) << 1);
                uint32_t h0 = pack_hi(acc[t][j][0], acc[t][j][1]);
                uint32_t l0 = pack_lo(acc[t][j][0], acc[t][j][1], h0);
                uint32_t h1 = pack_hi(acc[t][j][2], acc[t][j][3]);
                uint32_t l1 = pack_lo(acc[t][j][2], acc[t][j][3], h1);
                *(uint32_t*)&vh[(size_t)row * C_ + col]       = h0;
                *(uint32_t*)&vl[(size_t)row * C_ + col]       = l0;
                *(uint32_t*)&vh[(size_t)(row + 8) * C_ + col] = h1;
                *(uint32_t*)&vl[(size_t)(row + 8) * C_ + col] = l1;
            }
        }
    } else {
        // ---- Q/K epilogue: stage tile -> rmsnorm + rope -> bf16 hi/lo ----
        float* ft = (float*)smg;    // [128][FTS]
        #pragma unroll
        for (int t = 0; t < 2; t++) {
            int rl0 = warp_m * 32 + t * 16 + (lane >> 2);
            #pragma unroll
            for (int j = 0; j < 8; j++) {
                int cl = warp_n * 64 + j * 8 + ((lane & 3) << 1);
                ft[rl0 * FTS + cl]           = acc[t][j][0];
                ft[rl0 * FTS + cl + 1]       = acc[t][j][1];
                ft[(rl0 + 8) * FTS + cl]     = acc[t][j][2];
                ft[(rl0 + 8) * FTS + cl + 1] = acc[t][j][3];
            }
        }
        __syncthreads();

        const int r  = tid >> 1;
        const int hh = tid & 1;
        const int cb = hh * 32;
        const float* fr = ft + r * FTS;

        float ss = 0.f;
        #pragma unroll
        for (int i2 = 0; i2 < 32; i2++) {
            float a = fr[cb + i2];
            float b = fr[cb + 64 + i2];
            ss += a * a + b * b;
        }
        ss += __shfl_xor_sync(0xffffffffu, ss, 1);
        float rms = rsqrtf(ss * (1.0f / 128.0f) + 1.1920929e-7f);

        const int grow = bm * 128 + r;
        const int t    = grow & (T_ - 1);
        __nv_bfloat16* Oh = kind ? kh : qh;
        __nv_bfloat16* Ol = kind ? kl : ql;
        const size_t rb = (size_t)grow * C_ + lbn * 128;

        #pragma unroll
        for (int i2 = 0; i2 < 32; i2 += 2) {
            int c0 = cb + i2;
            float a0 = fr[c0] * rms,     b0 = fr[c0 + 64] * rms;
            float a1 = fr[c0 + 1] * rms, b1 = fr[c0 + 65] * rms;
            float co0 = cs[t * 64 + c0], si0 = sn[t * 64 + c0];
            float co1 = cs[t * 64 + c0 + 1], si1 = sn[t * 64 + c0 + 1];
            float y10 =  a0 * co0 + b0 * si0;
            float y11 =  a1 * co1 + b1 * si1;
            float y20 = -a0 * si0 + b0 * co0;
            float y21 = -a1 * si1 + b1 * co1;
            uint32_t h1p = pack_hi(y10, y11);
            uint32_t h2p = pack_hi(y20, y21);
            *(uint32_t*)&Oh[rb + c0]      = h1p;
            *(uint32_t*)&Ol[rb + c0]      = pack_lo(y10, y11, h1p);
            *(uint32_t*)&Oh[rb + c0 + 64] = h2p;
            *(uint32_t*)&Ol[rb + c0 + 64] = pack_lo(y20, y21, h2p);
        }
    }
}

// ---------------------------------------------------------------------------
// Output-projection GEMM (fp32 out): C[M,N] = A[M,K] @ B[N,K]^T
// ---------------------------------------------------------------------------
__global__ __launch_bounds__(256, 2) void bgemm3(
    const __nv_bfloat16* __restrict__ Ah, const __nv_bfloat16* __restrict__ Al,
    const __nv_bfloat16* __restrict__ Bh, const __nv_bfloat16* __restrict__ Bl,
    float* __restrict__ Cc, int Mm, int Nn, int K)
{
    extern __shared__ __align__(1024) char smg[];
    const int tid = threadIdx.x, lane = tid & 31, wid = tid >> 5;
    const int warp_m = wid & 3;
    const int warp_n = wid >> 2;
    const int bm = blockIdx.y, bn = blockIdx.x;
    const uint32_t sb = (uint32_t)__cvta_generic_to_shared(smg);

    float acc[2][8][4];
    #pragma unroll
    for (int i = 0; i < 2; i++)
        #pragma unroll
        for (int j = 0; j < 8; j++)
            #pragma unroll
            for (int e = 0; e < 4; e++) acc[i][j][e] = 0.f;

    const __nv_bfloat16* srcs[4] = { Ah, Al, Bh, Bl };

    auto issue = [&](int s, int k0) {
        const uint32_t st = sb + s * G3_STAGE;
        #pragma unroll
        for (int it = 0; it < 8; it++) {
            int j   = tid + it * 256;
            int sub = j >> 9;
            int cid = j & 511;
            int r   = cid >> 2;
            int ch  = cid & 3;
            int grow = (sub < 2 ? bm : bn) * 128 + r;
            const __nv_bfloat16* g = srcs[sub] + (size_t)grow * K + k0 + ch * 8;
            cp16(st + sub * G3_SUB + swz64((uint32_t)(r * 64 + ch * 16)), g);
        }
        asm volatile("cp.async.commit_group;");
    };

    const int NS = K / 32;
    issue(0, 0);
    issue(1, 32);

    const int mlane = lane & 15;
    const int aoff  = (lane >> 4) << 3;
    const int nlane = (lane & 7) + ((lane >> 4) << 3);
    const int klBo  = ((lane >> 3) & 1) << 3;

    for (int i = 0; i < NS; i++) {
        if (i == NS - 1) { asm volatile("cp.async.wait_group 0;"); }
        else             { asm volatile("cp.async.wait_group 1;"); }
        __syncthreads();
        if (i + 2 < NS) issue((i + 2) % 3, (i + 2) * 32);

        const uint32_t st = sb + (i % 3) * G3_STAGE;
        #pragma unroll
        for (int kk = 0; kk < 32; kk += 16) {
            uint32_t ah[2][4], al[2][4], b[8][2];
            #pragma unroll
            for (int t = 0; t < 2; t++) {
                uint32_t rb = (uint32_t)((warp_m * 32 + t * 16 + mlane) * 64 + (kk + aoff) * 2);
                ldmx4(ah[t][0], ah[t][1], ah[t][2], ah[t][3], st + 0 * G3_SUB + swz64(rb));
                ldmx4(al[t][0], al[t][1], al[t][2], al[t][3], st + 1 * G3_SUB + swz64(rb));
            }
            #pragma unroll
            for (int jt = 0; jt < 4; jt++) {
                uint32_t rb = (uint32_t)((warp_n * 64 + jt * 16 + nlane) * 64 + (kk + klBo) * 2);
                ldmx4(b[2*jt][0], b[2*jt][1], b[2*jt+1][0], b[2*jt+1][1], st + 2 * G3_SUB + swz64(rb));
            }
            #pragma unroll
            for (int t = 0; t < 2; t++)
                #pragma unroll
                for (int j = 0; j < 8; j++) mma16816(acc[t][j], ah[t], b[j]);
            #pragma unroll
            for (int t = 0; t < 2; t++)
                #pragma unroll
                for (int j = 0; j < 8; j++) mma16816(acc[t][j], al[t], b[j]);
            #pragma unroll
            for (int jt = 0; jt < 4; jt++) {
                uint32_t rb = (uint32_t)((warp_n * 64 + jt * 16 + nlane) * 64 + (kk + klBo) * 2);
                ldmx4(b[2*jt][0], b[2*jt][1], b[2*jt+1][0], b[2*jt+1][1], st + 3 * G3_SUB + swz64(rb));
            }
            #pragma unroll
            for (int t = 0; t < 2; t++)
                #pragma unroll
                for (int j = 0; j < 8; j++) mma16816(acc[t][j], ah[t], b[j]);
        }
        __syncthreads();
    }

    #pragma unroll
    for (int t = 0; t < 2; t++) {
        int row = bm * 128 + warp_m * 32 + t * 16 + (lane >> 2);
        #pragma unroll
        for (int j = 0; j < 8; j++) {
            int col = bn * 128 + warp_n * 64 + j * 8 + ((lane & 3) << 1);
            *(float2*)&Cc[(size_t)row * Nn + col]       = make_float2(acc[t][j][0], acc[t][j][1]);
            *(float2*)&Cc[(size_t)(row + 8) * Nn + col] = make_float2(acc[t][j][2], acc[t][j][3]);
        }
    }
}

// ---------------------------------------------------------------------------
// Tensor-core flash attention (causal), bf16 hi/lo 3-term, fp32 accum.
// Q fragments in registers; KV double-buffered.
// ---------------------------------------------------------------------------
#define SQ 136
#define FL_STAGE (4*64*SQ)
#define FL_KH 0
#define FL_KL (64*SQ)
#define FL_VH (128*SQ)
#define FL_VL (192*SQ)
#define FLASH_SMEM (2*FL_STAGE*2)        // 139264 bytes

__global__ __launch_bounds__(256, 1) void flash_bf16(
    const __nv_bfloat16* __restrict__ qh, const __nv_bfloat16* __restrict__ ql,
    const __nv_bfloat16* __restrict__ kh, const __nv_bfloat16* __restrict__ kl,
    const __nv_bfloat16* __restrict__ vh, const __nv_bfloat16* __restrict__ vl,
    __nv_bfloat16* __restrict__ oh, __nv_bfloat16* __restrict__ ol)
{
    extern __shared__ __nv_bfloat16 smf[];
    const int tid = threadIdx.x, lane = tid & 31, wid = tid >> 5;
    const int qb = gridDim.x - 1 - blockIdx.x;
    const int b  = blockIdx.y >> 4, h = blockIdx.y & 15;
    const uint32_t sb = (uint32_t)__cvta_generic_to_shared(smf);
    const size_t rowQ = (size_t)b * T_ + (size_t)qb * 128;
    const int colH = h * D_;

    const int wq = wid * 16;
    const int gq0 = qb * 128 + wq;
    const int mlane = lane & 15;
    const int aoff  = (lane >> 4) << 3;
    const int nlane = (lane & 7) + ((lane >> 4) << 3);
    const int klB   = ((lane >> 3) & 1) << 3;

    #pragma unroll
    for (int it = 0; it < 8; it++) {
        int idx = tid + it * 256;
        int r = idx >> 4, c = (idx & 15) << 3;
        size_t g = (rowQ + r) * C_ + colH + c;
        cp16(sb + 2u * (uint32_t)(r * SQ + c), qh + g);
        cp16(sb + 2u * (uint32_t)(128 * SQ + r * SQ + c), ql + g);
    }
    asm volatile("cp.async.commit_group;");
    asm volatile("cp.async.wait_group 0;");
    __syncthreads();

    uint32_t qfh[8][4], qfl[8][4];
    #pragma unroll
    for (int c = 0; c < 8; c++) {
        uint32_t ad = sb + 2u * (uint32_t)((wq + mlane) * SQ + c * 16 + aoff);
        ldmx4(qfh[c][0], qfh[c][1], qfh[c][2], qfh[c][3], ad);
        ldmx4(qfl[c][0], qfl[c][1], qfl[c][2], qfl[c][3], ad + 2u * (uint32_t)(128 * SQ));
    }
    __syncthreads();

    auto issueKV = [&](int s, int kt) {
        uint32_t st = s * FL_STAGE;
        #pragma unroll
        for (int it = 0; it < 4; it++) {
            int idx = tid + it * 256;
            int r = idx >> 4, c = (idx & 15) << 3;
            size_t g = ((size_t)b * T_ + (size_t)kt * 64 + r) * C_ + colH + c;
            uint32_t so = (uint32_t)(st + r * SQ + c);
            cp16(sb + 2u * (so + FL_KH), kh + g);
            cp16(sb + 2u * (so + FL_KL), kl + g);
            cp16(sb + 2u * (so + FL_VH), vh + g);
            cp16(sb + 2u * (so + FL_VL), vl + g);
        }
        asm volatile("cp.async.commit_group;");
    };

    issueKV(0, 0);

    const int nkt = 2 * qb + 2;
    const float scale = 0.088388347648318447f;

    float m0 = -CUDART_INF_F, m1 = -CUDART_INF_F, l0 = 0.f, l1 = 0.f;
    float oacc[16][4];
    #pragma unroll
    for (int j = 0; j < 16; j++)
        #pragma unroll
        for (int e = 0; e < 4; e++) oacc[j][e] = 0.f;

    int s = 0;
    for (int kt = 0; kt < nkt; kt++) {
        if (kt + 1 < nkt) {
            issueKV(s ^ 1, kt + 1);
            asm volatile("cp.async.wait_group 1;");
        } else {
            asm volatile("cp.async.wait_group 0;");
        }
        __syncthreads();

        const int kb = kt * 64;
        if (kb <= gq0 + 15) {
            const uint32_t st = s * FL_STAGE;

            float sacc[8][4];
            #pragma unroll
            for (int j = 0; j < 8; j++)
                #pragma unroll
                for (int e = 0; e < 4; e++) sacc[j][e] = 0.f;

            #pragma unroll
            for (int c = 0; c < 8; c++) {
                uint32_t bh2[8][2];
                #pragma unroll
                for (int jt = 0; jt < 4; jt++) {
                    uint32_t ad = sb + 2u * (uint32_t)(st + FL_KH + (jt * 16 + nlane) * SQ + c * 16 + klB);
                    ldmx4(bh2[2*jt][0], bh2[2*jt][1], bh2[2*jt+1][0], bh2[2*jt+1][1], ad);
                }
                #pragma unroll
                for (int j = 0; j < 8; j++) mma16816(sacc[j], qfh[c], bh2[j]);
                #pragma unroll
                for (int j = 0; j < 8; j++) mma16816(sacc[j], qfl[c], bh2[j]);
                #pragma unroll
                for (int jt = 0; jt < 4; jt++) {
                    uint32_t ad = sb + 2u * (uint32_t)(st + FL_KL + (jt * 16 + nlane) * SQ + c * 16 + klB);
                    ldmx4(bh2[2*jt][0], bh2[2*jt][1], bh2[2*jt+1][0], bh2[2*jt+1][1], ad);
                }
                #pragma unroll
                for (int j = 0; j < 8; j++) mma16816(sacc[j], qfh[c], bh2[j]);
            }

            const bool diag = (kb + 63 > gq0);
            const int r0 = gq0 + (lane >> 2), r1 = r0 + 8;
            float tm0 = -CUDART_INF_F, tm1 = -CUDART_INF_F;
            #pragma unroll
            for (int j = 0; j < 8; j++) {
                int cc = kb + j * 8 + ((lane & 3) << 1);
                float v0 = sacc[j][0] * scale, v1 = sacc[j][1] * scale;
                float v2 = sacc[j][2] * scale, v3 = sacc[j][3] * scale;
                if (diag) {
                    if (cc     > r0) v0 = -CUDART_INF_F;
                    if (cc + 1 > r0) v1 = -CUDART_INF_F;
                    if (cc     > r1) v2 = -CUDART_INF_F;
                    if (cc + 1 > r1) v3 = -CUDART_INF_F;
                }
                sacc[j][0] = v0; sacc[j][1] = v1; sacc[j][2] = v2; sacc[j][3] = v3;
                tm0 = fmaxf(tm0, fmaxf(v0, v1));
                tm1 = fmaxf(tm1, fmaxf(v2, v3));
            }
            tm0 = fmaxf(tm0, __shfl_xor_sync(0xffffffffu, tm0, 1));
            tm0 = fmaxf(tm0, __shfl_xor_sync(0xffffffffu, tm0, 2));
            tm1 = fmaxf(tm1, __shfl_xor_sync(0xffffffffu, tm1, 1));
            tm1 = fmaxf(tm1, __shfl_xor_sync(0xffffffffu, tm1, 2));
            float mn0 = fmaxf(m0, tm0), mn1 = fmaxf(m1, tm1);
            float a0 = __expf(m0 - mn0), a1 = __expf(m1 - mn1);
            float rs0 = 0.f, rs1 = 0.f;
            #pragma unroll
            for (int j = 0; j < 8; j++) {
                float p0 = __expf(sacc[j][0] - mn0);
                float p1 = __expf(sacc[j][1] - mn0);
                float p2 = __expf(sacc[j][2] - mn1);
                float p3 = __expf(sacc[j][3] - mn1);
                sacc[j][0] = p0; sacc[j][1] = p1; sacc[j][2] = p2; sacc[j][3] = p3;
                rs0 += p0 + p1; rs1 += p2 + p3;
            }
            rs0 += __shfl_xor_sync(0xffffffffu, rs0, 1);
            rs0 += __shfl_xor_sync(0xffffffffu, rs0, 2);
            rs1 += __shfl_xor_sync(0xffffffffu, rs1, 1);
            rs1 += __shfl_xor_sync(0xffffffffu, rs1, 2);
            l0 = l0 * a0 + rs0; l1 = l1 * a1 + rs1;
            m0 = mn0; m1 = mn1;
            #pragma unroll
            for (int j = 0; j < 16; j++) {
                oacc[j][0] *= a0; oacc[j][1] *= a0;
                oacc[j][2] *= a1; oacc[j][3] *= a1;
            }

            uint32_t ph[4][4], pl[4][4];
            #pragma unroll
            for (int c = 0; c < 4; c++) {
                ph[c][0] = pack_hi(sacc[2*c][0],   sacc[2*c][1]);
                pl[c][0] = pack_lo(sacc[2*c][0],   sacc[2*c][1],   ph[c][0]);
                ph[c][1] = pack_hi(sacc[2*c][2],   sacc[2*c][3]);
                pl[c][1] = pack_lo(sacc[2*c][2],   sacc[2*c][3],   ph[c][1]);
                ph[c][2] = pack_hi(sacc[2*c+1][0], sacc[2*c+1][1]);
                pl[c][2] = pack_lo(sacc[2*c+1][0], sacc[2*c+1][1], ph[c][2]);
                ph[c][3] = pack_hi(sacc[2*c+1][2], sacc[2*c+1][3]);
                pl[c][3] = pack_lo(sacc[2*c+1][2], sacc[2*c+1][3], ph[c][3]);
            }

            const int vrow = ((lane >> 3) & 1) * 8 + (lane & 7);
            const int vcol = (lane >> 4) << 3;
            #pragma unroll
            for (int c = 0; c < 4; c++) {
                #pragma unroll
                for (int dt = 0; dt < 8; dt++) {
                    uint32_t bv[4];
                    uint32_t ad = sb + 2u * (uint32_t)(st + FL_VH + (c * 16 + vrow) * SQ + dt * 16 + vcol);
                    ldmx4t(bv[0], bv[1], bv[2], bv[3], ad);
                    mma16816(oacc[2*dt],   ph[c], bv);
                    mma16816(oacc[2*dt+1], ph[c], bv + 2);
                    mma16816(oacc[2*dt],   pl[c], bv);
                    mma16816(oacc[2*dt+1], pl[c], bv + 2);
                }
                #pragma unroll
                for (int dt = 0; dt < 8; dt++) {
                    uint32_t bv[4];
                    uint32_t ad = sb + 2u * (uint32_t)(st + FL_VL + (c * 16 + vrow) * SQ + dt * 16 + vcol);
                    ldmx4t(bv[0], bv[1], bv[2], bv[3], ad);
                    mma16816(oacc[2*dt],   ph[c], bv);
                    mma16816(oacc[2*dt+1], ph[c], bv + 2);
                }
            }
        }
        __syncthreads();
        s ^= 1;
    }

    float inv0 = 1.0f / l0, inv1 = 1.0f / l1;
    size_t grow0 = (rowQ + wq + (lane >> 2)) * C_;
    size_t grow1 = grow0 + 8 * C_;
    #pragma unroll
    for (int j = 0; j < 16; j++) {
        int col = colH + j * 8 + ((lane & 3) << 1);
        float f0 = oacc[j][0] * inv0, f1 = oacc[j][1] * inv0;
        float f2 = oacc[j][2] * inv1, f3 = oacc[j][3] * inv1;
        uint32_t h0 = pack_hi(f0, f1), h1 = pack_hi(f2, f3);
        *(uint32_t*)&oh[grow0 + col] = h0;
        *(uint32_t*)&ol[grow0 + col] = pack_lo(f0, f1, h0);
        *(uint32_t*)&oh[grow1 + col] = h1;
        *(uint32_t*)&ol[grow1 + col] = pack_lo(f2, f3, h1);
    }
}

// ---------------------------------------------------------------------------
extern "C" void kernel_launch(void* const* d_in, const int* in_sizes, int n_in,
                              void* d_out, int out_size)
{
    (void)in_sizes; (void)n_in; (void)out_size;
    const float* x  = (const float*)d_in[0];
    const float* cs = (const float*)d_in[1];
    const float* sn = (const float*)d_in[2];
    float* out = (float*)d_out;

    __nv_bfloat16 *xh, *xl, *qh, *ql, *kh, *kl, *vh, *vl, *oh, *ol, *wh, *wl;
    cudaGetSymbolAddress((void**)&xh, g_xh);
    cudaGetSymbolAddress((void**)&xl, g_xl);
    cudaGetSymbolAddress((void**)&qh, g_qh);
    cudaGetSymbolAddress((void**)&ql, g_ql);
    cudaGetSymbolAddress((void**)&kh, g_kh);
    cudaGetSymbolAddress((void**)&kl, g_kl);
    cudaGetSymbolAddress((void**)&vh, g_vh);
    cudaGetSymbolAddress((void**)&vl, g_vl);
    cudaGetSymbolAddress((void**)&oh, g_oh);
    cudaGetSymbolAddress((void**)&ol, g_ol);
    cudaGetSymbolAddress((void**)&wh, g_wh);
    cudaGetSymbolAddress((void**)&wl, g_wl);

    cudaFuncSetAttribute(qkv_gemm, cudaFuncAttributeMaxDynamicSharedMemorySize, G3_SMEM);
    cudaFuncSetAttribute(bgemm3,   cudaFuncAttributeMaxDynamicSharedMemorySize, G3_SMEM);
    cudaFuncSetAttribute(flash_bf16, cudaFuncAttributeMaxDynamicSharedMemorySize, FLASH_SMEM);

    const int ntot = NX4 + 4 * NW4;
    split_all<<<ntot / 256, 256>>>((const float4*)x,
        (const float4*)d_in[3], (const float4*)d_in[4],
        (const float4*)d_in[5], (const float4*)d_in[6],
        (uint2*)xh, (uint2*)xl, (uint2*)wh, (uint2*)wl);

    qkv_gemm<<<dim3(48, 32), 256, G3_SMEM>>>(xh, xl, wh, wl, cs, sn,
                                             qh, ql, kh, kl, vh, vl);

    flash_bf16<<<dim3(T_/128, B_*H_), 256, FLASH_SMEM>>>(qh, ql, kh, kl, vh, vl, oh, ol);

    bgemm3<<<dim3(16, 32), 256, G3_SMEM>>>(oh, ol, wh + 3*(size_t)C_*C_, wl + 3*(size_t)C_*C_,
                                           out, M_, C_, C_);
}